// round 10
// baseline (speedup 1.0000x reference)
#include <cuda_runtime.h>
#include <math.h>

#define T_LEN 128
#define B_DIM 128
#define I_DIM 128
#define H_DIM 512
#define W_WIN 16
#define G4H   2048   // 4*H
#define IH    640    // I+H
#define KC_K  1152   // I + H + H (virtual K for cell GEMM)
#define NBLK  148    // persistent blocks (== min SM count)

// ---------------- scratch (device globals; no allocation allowed) ----------
__device__ float g_c[B_DIM * H_DIM];
__device__ float g_V[W_WIN * B_DIM * H_DIM];
__device__ float g_Q[B_DIM * H_DIM];

__device__ float g_h_hi[2][B_DIM * H_DIM];
__device__ float g_h_lo[2][B_DIM * H_DIM];
__device__ float g_c_hi[B_DIM * H_DIM];
__device__ float g_c_lo[B_DIM * H_DIM];
__device__ float g_attn_hi[B_DIM * H_DIM];
__device__ float g_attn_lo[B_DIM * H_DIM];
__device__ float g_x_hi[T_LEN * B_DIM * I_DIM];
__device__ float g_x_lo[T_LEN * B_DIM * I_DIM];

__device__ float g_Wc_hi[G4H * KC_K];
__device__ float g_Wc_lo[G4H * KC_K];
__device__ float g_Wq_hi[H_DIM * IH];
__device__ float g_Wq_lo[H_DIM * IH];
__device__ float g_Wv_hi[H_DIM * H_DIM];
__device__ float g_Wv_lo[H_DIM * H_DIM];

// grid barrier state
__device__ unsigned g_bar_count;
__device__ volatile unsigned g_bar_gen;

// ---------------- helpers ---------------------------------------------------
__device__ __forceinline__ unsigned smem_u32(const void* p) {
    return (unsigned)__cvta_generic_to_shared(p);
}
__device__ __forceinline__ void cp16(void* dst, const void* src) {
    asm volatile("cp.async.cg.shared.global [%0], [%1], 16;\n"
                 :: "r"(smem_u32(dst)), "l"(src));
}
__device__ __forceinline__ void cp_commit() {
    asm volatile("cp.async.commit_group;\n" ::: "memory");
}
__device__ __forceinline__ void cp_wait1() {
    asm volatile("cp.async.wait_group 1;\n" ::: "memory");
}
__device__ __forceinline__ void cp_wait0() {
    asm volatile("cp.async.wait_group 0;\n" ::: "memory");
}
__device__ __forceinline__ unsigned tf32u(float a) {
    unsigned r; asm("cvt.rna.tf32.f32 %0, %1;" : "=r"(r) : "f"(a)); return r;
}
__device__ __forceinline__ void mma8(float* c, const unsigned* a,
                                     unsigned b0, unsigned b1) {
    asm("mma.sync.aligned.m16n8k8.row.col.f32.tf32.tf32.f32 "
        "{%0,%1,%2,%3},{%4,%5,%6,%7},{%8,%9},{%0,%1,%2,%3};"
        : "+f"(c[0]), "+f"(c[1]), "+f"(c[2]), "+f"(c[3])
        : "r"(a[0]), "r"(a[1]), "r"(a[2]), "r"(a[3]), "r"(b0), "r"(b1));
}
__device__ __forceinline__ void split_store(float v, float* hi, float* lo) {
    float h = __uint_as_float(tf32u(v));
    *hi = h;
    *lo = __uint_as_float(tf32u(v - h));
}

// software grid barrier (all NBLK blocks co-resident: grid == one wave)
__device__ __forceinline__ void grid_sync() {
    __syncthreads();
    if (threadIdx.x == 0) {
        __threadfence();
        unsigned gen = g_bar_gen;
        unsigned prev = atomicAdd(&g_bar_count, 1u);
        if (prev == NBLK - 1) {
            g_bar_count = 0;
            __threadfence();
            g_bar_gen = gen + 1;
        } else {
            while (g_bar_gen == gen) { }
        }
        __threadfence();
    }
    __syncthreads();
}

// ---------------- init / prep (one-time) ------------------------------------
__global__ void init_kernel(const float* __restrict__ bv) {
    int idx = blockIdx.x * blockDim.x + threadIdx.x;
    int stride = gridDim.x * blockDim.x;
    for (int i = idx; i < B_DIM * H_DIM; i += stride) {
        g_h_hi[0][i] = 0.f; g_h_lo[0][i] = 0.f;
        g_c[i] = 0.f; g_c_hi[i] = 0.f; g_c_lo[i] = 0.f;
    }
    for (int i = idx; i < W_WIN * B_DIM * H_DIM; i += stride) {
        g_V[i] = bv[i % H_DIM];
    }
}
__global__ void prep_x(const float* __restrict__ x) {
    long total = (long)T_LEN * B_DIM * I_DIM;
    long stride = (long)gridDim.x * blockDim.x;
    for (long i = (long)blockIdx.x * blockDim.x + threadIdx.x; i < total; i += stride) {
        split_store(x[i], &g_x_hi[i], &g_x_lo[i]);
    }
}
__global__ void prep_wc(const float* __restrict__ Wi,
                        const float* __restrict__ Wh,
                        const float* __restrict__ Wa) {
    long total = (long)G4H * KC_K;
    long stride = (long)gridDim.x * blockDim.x;
    for (long i = (long)blockIdx.x * blockDim.x + threadIdx.x; i < total; i += stride) {
        int n = (int)(i / KC_K), k = (int)(i % KC_K);
        float w;
        if (k < I_DIM)   w = Wi[(size_t)k * G4H + n];
        else if (k < IH) w = Wh[(size_t)(k - I_DIM) * G4H + n];
        else             w = Wa[(size_t)(k - IH) * G4H + n];
        split_store(w, &g_Wc_hi[i], &g_Wc_lo[i]);
    }
}
__global__ void prep_wqv(const float* __restrict__ Wq,
                         const float* __restrict__ Wv) {
    long totq = (long)H_DIM * IH;
    long totv = (long)H_DIM * H_DIM;
    long stride = (long)gridDim.x * blockDim.x;
    for (long i = (long)blockIdx.x * blockDim.x + threadIdx.x; i < totq + totv; i += stride) {
        if (i < totq) {
            int n = (int)(i / IH), k = (int)(i % IH);
            split_store(Wq[(size_t)k * H_DIM + n], &g_Wq_hi[i], &g_Wq_lo[i]);
        } else {
            long j = i - totq;
            int n = (int)(j / H_DIM), k = (int)(j % H_DIM);
            split_store(Wv[(size_t)k * H_DIM + n], &g_Wv_hi[j], &g_Wv_lo[j]);
        }
    }
}

// ---------------- persistent scan kernel ------------------------------------
// 148 blocks x 128 threads. Per step:
//   phase A: 128 tiles (64 Q-GEMM + 64 V-GEMM), M32 x N32
//   phase B: 128 batch blocks (softmax+attn)
//   phase C: 256 tiles (cell GEMM M32 x [4 gates x 8 j]) + LSTM pointwise
__global__ __launch_bounds__(128) void larnn_scan(
    const float* __restrict__ bq, const float* __restrict__ bv,
    const float* __restrict__ bi, const float* __restrict__ ba,
    float* __restrict__ out)
{
    __shared__ float Ah[2][32][36], Al[2][32][36];
    __shared__ float Bh[2][32][36], Bl[2][32][36];
    __shared__ float sP[32][33];
    __shared__ float kbQ[H_DIM];
    __shared__ float kbS[W_WIN], kbPr[W_WIN];

    const int bid  = blockIdx.x;
    const int tid  = threadIdx.x;
    const int lane = tid & 31;
    const int warp = tid >> 5;
    const int mrow = (warp & 1) * 16;
    const int ncol = (warp >> 1) * 16;
    const int g    = lane >> 2, tg = lane & 3;

    for (int t = 0; t < T_LEN; t++) {
        const float* __restrict__ xhi = g_x_hi + (size_t)t * B_DIM * I_DIM;
        const float* __restrict__ xlo = g_x_lo + (size_t)t * B_DIM * I_DIM;
        const float* __restrict__ hhi = g_h_hi[t & 1];
        const float* __restrict__ hlo = g_h_lo[t & 1];
        float* __restrict__ hohi = g_h_hi[(t + 1) & 1];
        float* __restrict__ holo = g_h_lo[(t + 1) & 1];

        // ============ phase A: Q-GEMM + V-GEMM (128 tiles) ============
        for (int blk = bid; blk < 128; blk += NBLK) {
            const bool isQ = (blk < 64);
            const int tb = blk & 63;
            const int m0 = (tb >> 4) * 32;
            const int n0 = (tb & 15) * 32;
            const float* __restrict__ WH = isQ ? g_Wq_hi : g_Wv_hi;
            const float* __restrict__ WL = isQ ? g_Wq_lo : g_Wv_lo;
            const int Ktot = isQ ? IH : H_DIM;
            const int nt   = Ktot / 32;

            auto issue = [&](int it, int s) {
                const int kk = it * 32;
                #pragma unroll
                for (int l = 0; l < 2; l++) {
                    int id = tid + l * 128;
                    int r = id >> 3, c4 = (id & 7) * 4;
                    const float *ph, *pl;
                    if (isQ) {
                        int gk = kk + c4;
                        if (gk < I_DIM) {
                            ph = xhi + (size_t)(m0 + r) * I_DIM + gk;
                            pl = xlo + (size_t)(m0 + r) * I_DIM + gk;
                        } else {
                            ph = hhi + (size_t)(m0 + r) * H_DIM + (gk - I_DIM);
                            pl = hlo + (size_t)(m0 + r) * H_DIM + (gk - I_DIM);
                        }
                    } else {
                        ph = g_c_hi + (size_t)(m0 + r) * H_DIM + kk + c4;
                        pl = g_c_lo + (size_t)(m0 + r) * H_DIM + kk + c4;
                    }
                    cp16(&Ah[s][r][c4], ph);
                    cp16(&Al[s][r][c4], pl);
                }
                #pragma unroll
                for (int l = 0; l < 2; l++) {
                    int id = tid + l * 128;
                    int r = id >> 3, c4 = (id & 7) * 4;
                    size_t off = (size_t)(n0 + r) * Ktot + kk + c4;
                    cp16(&Bh[s][r][c4], WH + off);
                    cp16(&Bl[s][r][c4], WL + off);
                }
                cp_commit();
            };

            float cHH[2][4] = {}, cLH[2][4] = {}, cHL[2][4] = {};
            issue(0, 0);
            for (int it = 0; it < nt; it++) {
                const int s = it & 1;
                if (it + 1 < nt) { issue(it + 1, s ^ 1); cp_wait1(); }
                else             { cp_wait0(); }
                __syncthreads();
                #pragma unroll
                for (int k8 = 0; k8 < 4; k8++) {
                    const int k0 = k8 * 8;
                    unsigned ah[4], al[4];
                    ah[0] = __float_as_uint(Ah[s][mrow + g][k0 + tg]);
                    ah[1] = __float_as_uint(Ah[s][mrow + g + 8][k0 + tg]);
                    ah[2] = __float_as_uint(Ah[s][mrow + g][k0 + tg + 4]);
                    ah[3] = __float_as_uint(Ah[s][mrow + g + 8][k0 + tg + 4]);
                    al[0] = __float_as_uint(Al[s][mrow + g][k0 + tg]);
                    al[1] = __float_as_uint(Al[s][mrow + g + 8][k0 + tg]);
                    al[2] = __float_as_uint(Al[s][mrow + g][k0 + tg + 4]);
                    al[3] = __float_as_uint(Al[s][mrow + g + 8][k0 + tg + 4]);
                    #pragma unroll
                    for (int ns = 0; ns < 2; ns++) {
                        int n = ncol + ns * 8 + g;
                        unsigned bh0 = __float_as_uint(Bh[s][n][k0 + tg]);
                        unsigned bh1 = __float_as_uint(Bh[s][n][k0 + tg + 4]);
                        unsigned bl0 = __float_as_uint(Bl[s][n][k0 + tg]);
                        unsigned bl1 = __float_as_uint(Bl[s][n][k0 + tg + 4]);
                        mma8(cHH[ns], ah, bh0, bh1);
                        mma8(cLH[ns], al, bh0, bh1);
                        mma8(cHL[ns], ah, bl0, bl1);
                    }
                }
                __syncthreads();
            }

            const float* bias = isQ ? bq : bv;
            float* outp = isQ ? g_Q : (g_V + (size_t)(t % W_WIN) * B_DIM * H_DIM);
            #pragma unroll
            for (int ns = 0; ns < 2; ns++) {
                float a0 = cHH[ns][0] + cLH[ns][0] + cHL[ns][0];
                float a1 = cHH[ns][1] + cLH[ns][1] + cHL[ns][1];
                float a2 = cHH[ns][2] + cLH[ns][2] + cHL[ns][2];
                float a3 = cHH[ns][3] + cLH[ns][3] + cHL[ns][3];
                int col = n0 + ncol + ns * 8 + 2 * tg;
                int r0 = m0 + mrow + g, r1 = r0 + 8;
                outp[(size_t)r0 * H_DIM + col]     = a0 + bias[col];
                outp[(size_t)r0 * H_DIM + col + 1] = a1 + bias[col + 1];
                outp[(size_t)r1 * H_DIM + col]     = a2 + bias[col];
                outp[(size_t)r1 * H_DIM + col + 1] = a3 + bias[col + 1];
            }
        }
        grid_sync();

        // ============ phase B: softmax + attn (128 batches) ============
        for (int b = bid; b < B_DIM; b += NBLK) {
            const float inv_sqrt_dk = 0.044194173824159216f;
            for (int j = tid; j < H_DIM; j += 128) kbQ[j] = g_Q[(size_t)b * H_DIM + j];
            __syncthreads();

            int nv = (t + 1 < W_WIN) ? (t + 1) : W_WIN;
            for (int w = warp; w < nv; w += 4) {
                const float* Vp = g_V + (size_t)(w * B_DIM + b) * H_DIM;
                float p = 0.f;
                for (int j = lane; j < H_DIM; j += 32) p += kbQ[j] * Vp[j];
                #pragma unroll
                for (int o = 16; o > 0; o >>= 1) p += __shfl_xor_sync(0xffffffffu, p, o);
                if (lane == 0) kbS[w] = p * inv_sqrt_dk;
            }
            __syncthreads();
            if (tid == 0) {
                float m = kbS[0];
                for (int w = 1; w < nv; w++) m = fmaxf(m, kbS[w]);
                float sum = 0.f;
                for (int w = 0; w < nv; w++) { float e = expf(kbS[w] - m); kbPr[w] = e; sum += e; }
                float inv = 1.f / sum;
                for (int w = 0; w < nv; w++) kbPr[w] *= inv;
            }
            __syncthreads();
            for (int j = tid; j < H_DIM; j += 128) {
                float a = 0.f;
                for (int w = 0; w < nv; w++)
                    a += kbPr[w] * g_V[(size_t)(w * B_DIM + b) * H_DIM + j];
                size_t idx = (size_t)b * H_DIM + j;
                split_store(a, &g_attn_hi[idx], &g_attn_lo[idx]);
            }
            __syncthreads();
        }
        grid_sync();

        // ============ phase C: cell GEMM + LSTM pointwise (256 tiles) ========
        for (int blk = bid; blk < 256; blk += NBLK) {
            const int m0 = (blk >> 6) * 32;
            const int j0 = (blk & 63) * 8;

            auto issueC = [&](int it, int s) {
                const int kk = it * 32;
                const float *Shi, *Slo; int ldA, koff;
                if (kk < I_DIM)   { Shi = xhi;       Slo = xlo;       ldA = I_DIM; koff = kk; }
                else if (kk < IH) { Shi = hhi;       Slo = hlo;       ldA = H_DIM; koff = kk - I_DIM; }
                else              { Shi = g_attn_hi; Slo = g_attn_lo; ldA = H_DIM; koff = kk - IH; }
                #pragma unroll
                for (int l = 0; l < 2; l++) {
                    int id = tid + l * 128;
                    int r = id >> 3, c4 = (id & 7) * 4;
                    cp16(&Ah[s][r][c4], Shi + (size_t)(m0 + r) * ldA + koff + c4);
                    cp16(&Al[s][r][c4], Slo + (size_t)(m0 + r) * ldA + koff + c4);
                }
                #pragma unroll
                for (int l = 0; l < 2; l++) {
                    int id = tid + l * 128;
                    int r = id >> 3, c4 = (id & 7) * 4;
                    int gn = (r >> 3) * H_DIM + j0 + (r & 7);
                    size_t off = (size_t)gn * KC_K + kk + c4;
                    cp16(&Bh[s][r][c4], g_Wc_hi + off);
                    cp16(&Bl[s][r][c4], g_Wc_lo + off);
                }
                cp_commit();
            };

            float cHH[2][4] = {}, cLH[2][4] = {}, cHL[2][4] = {};
            const int nt = KC_K / 32;
            issueC(0, 0);
            for (int it = 0; it < nt; it++) {
                const int s = it & 1;
                if (it + 1 < nt) { issueC(it + 1, s ^ 1); cp_wait1(); }
                else             { cp_wait0(); }
                __syncthreads();
                #pragma unroll
                for (int k8 = 0; k8 < 4; k8++) {
                    const int k0 = k8 * 8;
                    unsigned ah[4], al[4];
                    ah[0] = __float_as_uint(Ah[s][mrow + g][k0 + tg]);
                    ah[1] = __float_as_uint(Ah[s][mrow + g + 8][k0 + tg]);
                    ah[2] = __float_as_uint(Ah[s][mrow + g][k0 + tg + 4]);
                    ah[3] = __float_as_uint(Ah[s][mrow + g + 8][k0 + tg + 4]);
                    al[0] = __float_as_uint(Al[s][mrow + g][k0 + tg]);
                    al[1] = __float_as_uint(Al[s][mrow + g + 8][k0 + tg]);
                    al[2] = __float_as_uint(Al[s][mrow + g][k0 + tg + 4]);
                    al[3] = __float_as_uint(Al[s][mrow + g + 8][k0 + tg + 4]);
                    #pragma unroll
                    for (int ns = 0; ns < 2; ns++) {
                        int n = ncol + ns * 8 + g;
                        unsigned bh0 = __float_as_uint(Bh[s][n][k0 + tg]);
                        unsigned bh1 = __float_as_uint(Bh[s][n][k0 + tg + 4]);
                        unsigned bl0 = __float_as_uint(Bl[s][n][k0 + tg]);
                        unsigned bl1 = __float_as_uint(Bl[s][n][k0 + tg + 4]);
                        mma8(cHH[ns], ah, bh0, bh1);
                        mma8(cLH[ns], al, bh0, bh1);
                        mma8(cHL[ns], ah, bl0, bl1);
                    }
                }
                __syncthreads();
            }

            #pragma unroll
            for (int ns = 0; ns < 2; ns++) {
                int col0 = ncol + ns * 8 + 2 * tg;
                sP[mrow + g][col0]         = cHH[ns][0] + cLH[ns][0] + cHL[ns][0];
                sP[mrow + g][col0 + 1]     = cHH[ns][1] + cLH[ns][1] + cHL[ns][1];
                sP[mrow + g + 8][col0]     = cHH[ns][2] + cLH[ns][2] + cHL[ns][2];
                sP[mrow + g + 8][col0 + 1] = cHH[ns][3] + cLH[ns][3] + cHL[ns][3];
            }
            __syncthreads();

            const int row = tid >> 3;
            const int jj  = tid & 7;
            const int j   = j0 + jj;
            float bii = bi[j]             + ba[j];
            float bif = bi[H_DIM + j]     + ba[H_DIM + j];
            float bio = bi[2 * H_DIM + j] + ba[2 * H_DIM + j];
            float big = bi[3 * H_DIM + j] + ba[3 * H_DIM + j];

            #pragma unroll
            for (int half = 0; half < 2; half++) {
                int r = row + half * 16;
                int b = m0 + r;
                float pi = sP[r][jj]      + bii;
                float pf = sP[r][8 + jj]  + bif;
                float po = sP[r][16 + jj] + bio;
                float pg = sP[r][24 + jj] + big;

                float ig = 1.f / (1.f + expf(-pi));
                float fg = 1.f / (1.f + expf(-pf));
                float og = 1.f / (1.f + expf(-po));
                float gg = tanhf(pg);

                size_t idx = (size_t)b * H_DIM + j;
                float cn = g_c[idx] * fg + ig * gg;
                float hn = og * tanhf(cn);

                g_c[idx] = cn;
                split_store(cn, &g_c_hi[idx], &g_c_lo[idx]);
                split_store(hn, &hohi[idx], &holo[idx]);
                out[(size_t)t * B_DIM * H_DIM + idx] = hn;
            }
            __syncthreads();
        }
        grid_sync();
    }
}

// ---------------- launcher --------------------------------------------------
extern "C" void kernel_launch(void* const* d_in, const int* in_sizes, int n_in,
                              void* d_out, int out_size) {
    const float* x  = (const float*)d_in[0];
    const float* Wi = (const float*)d_in[1];
    const float* bi = (const float*)d_in[2];
    const float* Wh = (const float*)d_in[3];
    const float* Wv = (const float*)d_in[4];
    const float* bv = (const float*)d_in[5];
    const float* Wq = (const float*)d_in[6];
    const float* bq = (const float*)d_in[7];
    const float* Wa = (const float*)d_in[8];
    const float* ba = (const float*)d_in[9];
    float* out = (float*)d_out;

    init_kernel<<<1024, 256>>>(bv);
    prep_x<<<2048, 256>>>(x);
    prep_wc<<<2048, 256>>>(Wi, Wh, Wa);
    prep_wqv<<<1024, 256>>>(Wq, Wv);
    larnn_scan<<<NBLK, 128>>>(bq, bv, bi, ba, out);
}

// round 12
// speedup vs baseline: 1.4308x; 1.4308x over previous
#include <cuda_runtime.h>
#include <cuda_fp16.h>
#include <math.h>

#define T_LEN 128
#define B_DIM 128
#define I_DIM 128
#define H_DIM 512
#define W_WIN 16
#define G4H   2048   // 4*H
#define IH    640    // I+H
#define KC_K  1152   // I + H + H (virtual K for cell GEMM)
#define INV1024 0.0009765625f

// ---------------- scratch (device globals; no allocation allowed) ----------
__device__ float g_c[B_DIM * H_DIM];               // cell state fp32 master
__device__ float g_V[W_WIN * B_DIM * H_DIM];       // V cache fp32
__device__ float g_Q[B_DIM * H_DIM];               // Q fp32

// fp16-split activations (hi, lo*1024), maintained by epilogues
__device__ __half g_h_hi[2][B_DIM * H_DIM];
__device__ __half g_h_lo[2][B_DIM * H_DIM];
__device__ __half g_c_hi[B_DIM * H_DIM];
__device__ __half g_c_lo[B_DIM * H_DIM];
__device__ __half g_attn_hi[B_DIM * H_DIM];
__device__ __half g_attn_lo[B_DIM * H_DIM];
__device__ __half g_x_hi[T_LEN * B_DIM * I_DIM];
__device__ __half g_x_lo[T_LEN * B_DIM * I_DIM];

// transposed + fp16-split weights (computed once per call), [n][k]
__device__ __half g_Wc_hi[G4H * KC_K];
__device__ __half g_Wc_lo[G4H * KC_K];
__device__ __half g_Wq_hi[H_DIM * IH];
__device__ __half g_Wq_lo[H_DIM * IH];
__device__ __half g_Wv_hi[H_DIM * H_DIM];
__device__ __half g_Wv_lo[H_DIM * H_DIM];

// ---------------- helpers ---------------------------------------------------
__device__ __forceinline__ unsigned smem_u32(const void* p) {
    return (unsigned)__cvta_generic_to_shared(p);
}
__device__ __forceinline__ void cp16(void* dst, const void* src) {
    asm volatile("cp.async.cg.shared.global [%0], [%1], 16;\n"
                 :: "r"(smem_u32(dst)), "l"(src));
}
__device__ __forceinline__ void cp_commit() {
    asm volatile("cp.async.commit_group;\n" ::: "memory");
}
__device__ __forceinline__ void cp_wait1() {
    asm volatile("cp.async.wait_group 1;\n" ::: "memory");
}
__device__ __forceinline__ void cp_wait0() {
    asm volatile("cp.async.wait_group 0;\n" ::: "memory");
}
// D += A(m16k16,row) * B(k16n8,col)   fp16 in, fp32 accum
__device__ __forceinline__ void hmma(float* c, const unsigned* a,
                                     unsigned b0, unsigned b1) {
    asm("mma.sync.aligned.m16n8k16.row.col.f32.f16.f16.f32 "
        "{%0,%1,%2,%3},{%4,%5,%6,%7},{%8,%9},{%0,%1,%2,%3};"
        : "+f"(c[0]), "+f"(c[1]), "+f"(c[2]), "+f"(c[3])
        : "r"(a[0]), "r"(a[1]), "r"(a[2]), "r"(a[3]), "r"(b0), "r"(b1));
}
// v = hi + lo/1024 ; lo stored pre-scaled so it stays in fp16 normal range
__device__ __forceinline__ void split_store_h(float v, __half* hi, __half* lo) {
    __half h = __float2half_rn(v);
    *hi = h;
    *lo = __float2half_rn((v - __half2float(h)) * 1024.0f);
}
#define U32AT(x) (*(const unsigned*)&(x))

// ---------------- init: h=0, c=0 (and splits), V[w][b][:] = bv --------------
__global__ void init_kernel(const float* __restrict__ bv) {
    int idx = blockIdx.x * blockDim.x + threadIdx.x;
    int stride = gridDim.x * blockDim.x;
    __half z = __float2half(0.f);
    for (int i = idx; i < B_DIM * H_DIM; i += stride) {
        g_h_hi[0][i] = z; g_h_lo[0][i] = z;
        g_c[i] = 0.f; g_c_hi[i] = z; g_c_lo[i] = z;
    }
    for (int i = idx; i < W_WIN * B_DIM * H_DIM; i += stride) {
        g_V[i] = bv[i % H_DIM];
    }
}

// ---------------- prep kernels ----------------------------------------------
__global__ void prep_x(const float* __restrict__ x) {
    long total = (long)T_LEN * B_DIM * I_DIM;
    long stride = (long)gridDim.x * blockDim.x;
    for (long i = (long)blockIdx.x * blockDim.x + threadIdx.x; i < total; i += stride) {
        split_store_h(x[i], &g_x_hi[i], &g_x_lo[i]);
    }
}
__global__ void prep_wc(const float* __restrict__ Wi,
                        const float* __restrict__ Wh,
                        const float* __restrict__ Wa) {
    long total = (long)G4H * KC_K;
    long stride = (long)gridDim.x * blockDim.x;
    for (long i = (long)blockIdx.x * blockDim.x + threadIdx.x; i < total; i += stride) {
        int n = (int)(i / KC_K), k = (int)(i % KC_K);
        float w;
        if (k < I_DIM)   w = Wi[(size_t)k * G4H + n];
        else if (k < IH) w = Wh[(size_t)(k - I_DIM) * G4H + n];
        else             w = Wa[(size_t)(k - IH) * G4H + n];
        split_store_h(w, &g_Wc_hi[i], &g_Wc_lo[i]);
    }
}
__global__ void prep_wqv(const float* __restrict__ Wq,
                         const float* __restrict__ Wv) {
    long totq = (long)H_DIM * IH;
    long totv = (long)H_DIM * H_DIM;
    long stride = (long)gridDim.x * blockDim.x;
    for (long i = (long)blockIdx.x * blockDim.x + threadIdx.x; i < totq + totv; i += stride) {
        if (i < totq) {
            int n = (int)(i / IH), k = (int)(i % IH);
            split_store_h(Wq[(size_t)k * H_DIM + n], &g_Wq_hi[i], &g_Wq_lo[i]);
        } else {
            long j = i - totq;
            int n = (int)(j / H_DIM), k = (int)(j % H_DIM);
            split_store_h(Wv[(size_t)k * H_DIM + n], &g_Wv_hi[j], &g_Wv_lo[j]);
        }
    }
}

// ---------------- KA: Q = [x_t|h] @ Wq + bq   AND   V[t%W] = c @ Wv + bv ----
// grid = 128 blocks x 128 threads (4 warps, 2x2 m16n16 each).
// Blocks 0..63 : Q-GEMM (M=128,N=512,K=640)  tile M32 x N32
// Blocks 64..127: V-GEMM (M=128,N=512,K=512)
__global__ __launch_bounds__(128) void ka_kernel(
    int t, const float* __restrict__ bq, const float* __restrict__ bv)
{
    __shared__ __half Ah[2][32][40], Al[2][32][40];
    __shared__ __half Bh[2][32][40], Bl[2][32][40];

    const int blk = blockIdx.x;
    const bool isQ = (blk < 64);
    const int bid = blk & 63;
    const int m0 = (bid >> 4) * 32;     // 4 M-tiles
    const int n0 = (bid & 15) * 32;     // 16 N-tiles

    const __half* __restrict__ xhi = g_x_hi + (size_t)t * B_DIM * I_DIM;
    const __half* __restrict__ xlo = g_x_lo + (size_t)t * B_DIM * I_DIM;
    const __half* __restrict__ hhi = g_h_hi[t & 1];
    const __half* __restrict__ hlo = g_h_lo[t & 1];
    const __half* __restrict__ WH  = isQ ? g_Wq_hi : g_Wv_hi;
    const __half* __restrict__ WL  = isQ ? g_Wq_lo : g_Wv_lo;
    const int Ktot = isQ ? IH : H_DIM;
    const int nt   = Ktot / 32;

    const int tid  = threadIdx.x;
    const int lane = tid & 31;
    const int warp = tid >> 5;
    const int mrow = (warp & 1) * 16;
    const int ncol = (warp >> 1) * 16;
    const int g    = lane >> 2, tg = lane & 3;

    const int ar  = tid >> 2;            // 0..31 row
    const int ac8 = (tid & 3) * 8;       // 8-half chunk

    auto issue = [&](int it, int s) {
        const int kk = it * 32;
        // A hi/lo: 32 rows x 32 halves -> 1 cp16/thread per plane
        {
            const __half *ph, *pl;
            if (isQ) {
                int gk = kk + ac8;
                if (gk < I_DIM) {
                    ph = xhi + (size_t)(m0 + ar) * I_DIM + gk;
                    pl = xlo + (size_t)(m0 + ar) * I_DIM + gk;
                } else {
                    ph = hhi + (size_t)(m0 + ar) * H_DIM + (gk - I_DIM);
                    pl = hlo + (size_t)(m0 + ar) * H_DIM + (gk - I_DIM);
                }
            } else {
                ph = g_c_hi + (size_t)(m0 + ar) * H_DIM + kk + ac8;
                pl = g_c_lo + (size_t)(m0 + ar) * H_DIM + kk + ac8;
            }
            cp16(&Ah[s][ar][ac8], ph);
            cp16(&Al[s][ar][ac8], pl);
        }
        // B hi/lo: 32 n-rows x 32 halves -> 1 cp16/thread per plane
        {
            size_t off = (size_t)(n0 + ar) * Ktot + kk + ac8;
            cp16(&Bh[s][ar][ac8], WH + off);
            cp16(&Bl[s][ar][ac8], WL + off);
        }
        cp_commit();
    };

    float cHH[2][4] = {}, cLH[2][4] = {}, cHL[2][4] = {};

    issue(0, 0);
    for (int it = 0; it < nt; it++) {
        const int s = it & 1;
        if (it + 1 < nt) { issue(it + 1, s ^ 1); cp_wait1(); }
        else             { cp_wait0(); }
        __syncthreads();

        #pragma unroll
        for (int ko = 0; ko < 32; ko += 16) {
            unsigned ah[4], al[4];
            ah[0] = U32AT(Ah[s][mrow + g][ko + 2 * tg]);
            ah[1] = U32AT(Ah[s][mrow + g + 8][ko + 2 * tg]);
            ah[2] = U32AT(Ah[s][mrow + g][ko + 2 * tg + 8]);
            ah[3] = U32AT(Ah[s][mrow + g + 8][ko + 2 * tg + 8]);
            al[0] = U32AT(Al[s][mrow + g][ko + 2 * tg]);
            al[1] = U32AT(Al[s][mrow + g + 8][ko + 2 * tg]);
            al[2] = U32AT(Al[s][mrow + g][ko + 2 * tg + 8]);
            al[3] = U32AT(Al[s][mrow + g + 8][ko + 2 * tg + 8]);

            #pragma unroll
            for (int ns = 0; ns < 2; ns++) {
                int n = ncol + ns * 8 + g;
                unsigned bh0 = U32AT(Bh[s][n][ko + 2 * tg]);
                unsigned bh1 = U32AT(Bh[s][n][ko + 2 * tg + 8]);
                unsigned bl0 = U32AT(Bl[s][n][ko + 2 * tg]);
                unsigned bl1 = U32AT(Bl[s][n][ko + 2 * tg + 8]);
                hmma(cHH[ns], ah, bh0, bh1);
                hmma(cLH[ns], al, bh0, bh1);
                hmma(cHL[ns], ah, bl0, bl1);
            }
        }
        __syncthreads();
    }

    const float* bias = isQ ? bq : bv;
    float* outp = isQ ? g_Q : (g_V + (size_t)(t % W_WIN) * B_DIM * H_DIM);
    #pragma unroll
    for (int ns = 0; ns < 2; ns++) {
        float a0 = cHH[ns][0] + (cLH[ns][0] + cHL[ns][0]) * INV1024;
        float a1 = cHH[ns][1] + (cLH[ns][1] + cHL[ns][1]) * INV1024;
        float a2 = cHH[ns][2] + (cLH[ns][2] + cHL[ns][2]) * INV1024;
        float a3 = cHH[ns][3] + (cLH[ns][3] + cHL[ns][3]) * INV1024;
        int col = n0 + ncol + ns * 8 + 2 * tg;
        int r0 = m0 + mrow + g, r1 = r0 + 8;
        outp[(size_t)r0 * H_DIM + col]     = a0 + bias[col];
        outp[(size_t)r0 * H_DIM + col + 1] = a1 + bias[col + 1];
        outp[(size_t)r1 * H_DIM + col]     = a2 + bias[col];
        outp[(size_t)r1 * H_DIM + col + 1] = a3 + bias[col + 1];
    }
}

// ---------------- KB: scores -> softmax -> attn (writes attn splits) --------
__global__ __launch_bounds__(128) void kb_kernel(int t) {
    const float inv_sqrt_dk = 0.044194173824159216f; // 1/sqrt(512)
    int b = blockIdx.x;
    int tid = threadIdx.x;
    __shared__ float sQ[H_DIM];
    __shared__ float sS[W_WIN];
    __shared__ float sP[W_WIN];

    for (int j = tid; j < H_DIM; j += 128) sQ[j] = g_Q[(size_t)b * H_DIM + j];
    __syncthreads();

    int nv = (t + 1 < W_WIN) ? (t + 1) : W_WIN;
    int warp = tid / 32, lane = tid % 32;
    for (int w = warp; w < nv; w += 4) {
        const float* Vp = g_V + (size_t)(w * B_DIM + b) * H_DIM;
        float p = 0.f;
        for (int j = lane; j < H_DIM; j += 32) p += sQ[j] * Vp[j];
        #pragma unroll
        for (int o = 16; o > 0; o >>= 1) p += __shfl_xor_sync(0xffffffffu, p, o);
        if (lane == 0) sS[w] = p * inv_sqrt_dk;
    }
    __syncthreads();
    if (tid == 0) {
        float m = sS[0];
        for (int w = 1; w < nv; w++) m = fmaxf(m, sS[w]);
        float sum = 0.f;
        for (int w = 0; w < nv; w++) { float e = expf(sS[w] - m); sP[w] = e; sum += e; }
        float inv = 1.f / sum;
        for (int w = 0; w < nv; w++) sP[w] *= inv;
    }
    __syncthreads();
    for (int j = tid; j < H_DIM; j += 128) {
        float a = 0.f;
        for (int w = 0; w < nv; w++)
            a += sP[w] * g_V[(size_t)(w * B_DIM + b) * H_DIM + j];
        size_t idx = (size_t)b * H_DIM + j;
        split_store_h(a, &g_attn_hi[idx], &g_attn_lo[idx]);
    }
}

// ---------------- KC: fused cell GEMM (fp16 mma) + LSTM pointwise -----------
// preact = [x|h|attn] @ Wc + biases, virtual K=1152.
// grid = 256 blocks (4 M-tiles x 64 j-tiles) x 128 threads.
// Tile: M=32 x N=32 (4 gates x 8 j). Warp 2x2: m16 x n16.
__global__ __launch_bounds__(128) void kc_kernel(
    int t,
    const float* __restrict__ bi, const float* __restrict__ ba,
    float* __restrict__ out)
{
    __shared__ __half Ah[2][32][40], Al[2][32][40];
    __shared__ __half Bh[2][32][40], Bl[2][32][40];
    __shared__ float sP[32][33];

    const int m0 = (blockIdx.x >> 6) * 32;  // 4 M-tiles
    const int j0 = (blockIdx.x & 63) * 8;   // 64 j-tiles

    const __half* __restrict__ xhi = g_x_hi + (size_t)t * B_DIM * I_DIM;
    const __half* __restrict__ xlo = g_x_lo + (size_t)t * B_DIM * I_DIM;
    const __half* __restrict__ hhi = g_h_hi[t & 1];
    const __half* __restrict__ hlo = g_h_lo[t & 1];
    __half* __restrict__ hohi = g_h_hi[(t + 1) & 1];
    __half* __restrict__ holo = g_h_lo[(t + 1) & 1];

    const int tid  = threadIdx.x;
    const int lane = tid & 31;
    const int warp = tid >> 5;
    const int mrow = (warp & 1) * 16;
    const int ncol = (warp >> 1) * 16;
    const int g    = lane >> 2, tg = lane & 3;

    const int ar  = tid >> 2;
    const int ac8 = (tid & 3) * 8;

    auto issue = [&](int it, int s) {
        const int kk = it * 32;
        const __half *Shi, *Slo; int ldA, koff;
        if (kk < I_DIM)   { Shi = xhi;       Slo = xlo;       ldA = I_DIM; koff = kk; }
        else if (kk < IH) { Shi = hhi;       Slo = hlo;       ldA = H_DIM; koff = kk - I_DIM; }
        else              { Shi = g_attn_hi; Slo = g_attn_lo; ldA = H_DIM; koff = kk - IH; }
        cp16(&Ah[s][ar][ac8], Shi + (size_t)(m0 + ar) * ldA + koff + ac8);
        cp16(&Al[s][ar][ac8], Slo + (size_t)(m0 + ar) * ldA + koff + ac8);
        {
            int gn = (ar >> 3) * H_DIM + j0 + (ar & 7);
            size_t off = (size_t)gn * KC_K + kk + ac8;
            cp16(&Bh[s][ar][ac8], g_Wc_hi + off);
            cp16(&Bl[s][ar][ac8], g_Wc_lo + off);
        }
        cp_commit();
    };

    float cHH[2][4] = {}, cLH[2][4] = {}, cHL[2][4] = {};

    const int nt = KC_K / 32;  // 36
    issue(0, 0);
    for (int it = 0; it < nt; it++) {
        const int s = it & 1;
        if (it + 1 < nt) { issue(it + 1, s ^ 1); cp_wait1(); }
        else             { cp_wait0(); }
        __syncthreads();

        #pragma unroll
        for (int ko = 0; ko < 32; ko += 16) {
            unsigned ah[4], al[4];
            ah[0] = U32AT(Ah[s][mrow + g][ko + 2 * tg]);
            ah[1] = U32AT(Ah[s][mrow + g + 8][ko + 2 * tg]);
            ah[2] = U32AT(Ah[s][mrow + g][ko + 2 * tg + 8]);
            ah[3] = U32AT(Ah[s][mrow + g + 8][ko + 2 * tg + 8]);
            al[0] = U32AT(Al[s][mrow + g][ko + 2 * tg]);
            al[1] = U32AT(Al[s][mrow + g + 8][ko + 2 * tg]);
            al[2] = U32AT(Al[s][mrow + g][ko + 2 * tg + 8]);
            al[3] = U32AT(Al[s][mrow + g + 8][ko + 2 * tg + 8]);

            #pragma unroll
            for (int ns = 0; ns < 2; ns++) {
                int n = ncol + ns * 8 + g;
                unsigned bh0 = U32AT(Bh[s][n][ko + 2 * tg]);
                unsigned bh1 = U32AT(Bh[s][n][ko + 2 * tg + 8]);
                unsigned bl0 = U32AT(Bl[s][n][ko + 2 * tg]);
                unsigned bl1 = U32AT(Bl[s][n][ko + 2 * tg + 8]);
                hmma(cHH[ns], ah, bh0, bh1);
                hmma(cLH[ns], al, bh0, bh1);
                hmma(cHL[ns], ah, bl0, bl1);
            }
        }
        __syncthreads();
    }

    // combine chains + exchange preact through smem
    #pragma unroll
    for (int ns = 0; ns < 2; ns++) {
        int col0 = ncol + ns * 8 + 2 * tg;
        sP[mrow + g][col0]         = cHH[ns][0] + (cLH[ns][0] + cHL[ns][0]) * INV1024;
        sP[mrow + g][col0 + 1]     = cHH[ns][1] + (cLH[ns][1] + cHL[ns][1]) * INV1024;
        sP[mrow + g + 8][col0]     = cHH[ns][2] + (cLH[ns][2] + cHL[ns][2]) * INV1024;
        sP[mrow + g + 8][col0 + 1] = cHH[ns][3] + (cLH[ns][3] + cHL[ns][3]) * INV1024;
    }
    __syncthreads();

    const int row = tid >> 3;          // 0..15
    const int jj  = tid & 7;           // 0..7
    const int j   = j0 + jj;

    float bii = bi[j]             + ba[j];
    float bif = bi[H_DIM + j]     + ba[H_DIM + j];
    float bio = bi[2 * H_DIM + j] + ba[2 * H_DIM + j];
    float big = bi[3 * H_DIM + j] + ba[3 * H_DIM + j];

    #pragma unroll
    for (int half = 0; half < 2; half++) {
        int r = row + half * 16;
        int b = m0 + r;
        float pi = sP[r][jj]      + bii;
        float pf = sP[r][8 + jj]  + bif;
        float po = sP[r][16 + jj] + bio;
        float pg = sP[r][24 + jj] + big;

        float ig = 1.f / (1.f + expf(-pi));
        float fg = 1.f / (1.f + expf(-pf));
        float og = 1.f / (1.f + expf(-po));
        float gg = tanhf(pg);

        size_t idx = (size_t)b * H_DIM + j;
        float cn = g_c[idx] * fg + ig * gg;
        float hn = og * tanhf(cn);

        g_c[idx] = cn;
        split_store_h(cn, &g_c_hi[idx], &g_c_lo[idx]);
        split_store_h(hn, &hohi[idx], &holo[idx]);
        out[(size_t)t * B_DIM * H_DIM + idx] = hn;
    }
}

// ---------------- launcher --------------------------------------------------
extern "C" void kernel_launch(void* const* d_in, const int* in_sizes, int n_in,
                              void* d_out, int out_size) {
    const float* x  = (const float*)d_in[0];
    const float* Wi = (const float*)d_in[1];
    const float* bi = (const float*)d_in[2];
    const float* Wh = (const float*)d_in[3];
    const float* Wv = (const float*)d_in[4];
    const float* bv = (const float*)d_in[5];
    const float* Wq = (const float*)d_in[6];
    const float* bq = (const float*)d_in[7];
    const float* Wa = (const float*)d_in[8];
    const float* ba = (const float*)d_in[9];
    float* out = (float*)d_out;

    init_kernel<<<1024, 256>>>(bv);
    prep_x<<<2048, 256>>>(x);
    prep_wc<<<2048, 256>>>(Wi, Wh, Wa);
    prep_wqv<<<1024, 256>>>(Wq, Wv);
    for (int t = 0; t < T_LEN; t++) {
        ka_kernel<<<128, 128>>>(t, bq, bv);
        kb_kernel<<<128, 128>>>(t);
        kc_kernel<<<256, 128>>>(t, bi, ba, out);
    }
}

// round 13
// speedup vs baseline: 1.4741x; 1.0303x over previous
#include <cuda_runtime.h>
#include <cuda_fp16.h>
#include <math.h>

#define T_LEN 128
#define B_DIM 128
#define I_DIM 128
#define H_DIM 512
#define W_WIN 16
#define G4H   2048   // 4*H
#define IH    640    // I+H
#define KC_K  1152   // I + H + H (virtual K for cell GEMM)
#define INV1024 0.0009765625f

// ---------------- scratch (device globals; no allocation allowed) ----------
__device__ float g_c[B_DIM * H_DIM];               // cell state fp32 master
__device__ float g_V[W_WIN * B_DIM * H_DIM];       // V cache fp32
__device__ float g_Q[B_DIM * H_DIM];               // Q fp32

// fp16-split activations (hi, lo*1024), maintained by epilogues
__device__ __half g_h_hi[2][B_DIM * H_DIM];
__device__ __half g_h_lo[2][B_DIM * H_DIM];
__device__ __half g_c_hi[B_DIM * H_DIM];
__device__ __half g_c_lo[B_DIM * H_DIM];
__device__ __half g_attn_hi[B_DIM * H_DIM];
__device__ __half g_attn_lo[B_DIM * H_DIM];
__device__ __half g_x_hi[T_LEN * B_DIM * I_DIM];
__device__ __half g_x_lo[T_LEN * B_DIM * I_DIM];

// transposed + fp16-split weights (computed once per call), [n][k]
__device__ __half g_Wc_hi[G4H * KC_K];
__device__ __half g_Wc_lo[G4H * KC_K];
__device__ __half g_Wq_hi[H_DIM * IH];
__device__ __half g_Wq_lo[H_DIM * IH];
__device__ __half g_Wv_hi[H_DIM * H_DIM];
__device__ __half g_Wv_lo[H_DIM * H_DIM];

// ---------------- helpers ---------------------------------------------------
__device__ __forceinline__ unsigned smem_u32(const void* p) {
    return (unsigned)__cvta_generic_to_shared(p);
}
__device__ __forceinline__ void cp16(void* dst, const void* src) {
    asm volatile("cp.async.cg.shared.global [%0], [%1], 16;\n"
                 :: "r"(smem_u32(dst)), "l"(src));
}
__device__ __forceinline__ void cp_commit() {
    asm volatile("cp.async.commit_group;\n" ::: "memory");
}
__device__ __forceinline__ void cp_wait1() {
    asm volatile("cp.async.wait_group 1;\n" ::: "memory");
}
__device__ __forceinline__ void cp_wait0() {
    asm volatile("cp.async.wait_group 0;\n" ::: "memory");
}
// D += A(m16k16,row) * B(k16n8,col)   fp16 in, fp32 accum
__device__ __forceinline__ void hmma(float* c, const unsigned* a,
                                     unsigned b0, unsigned b1) {
    asm("mma.sync.aligned.m16n8k16.row.col.f32.f16.f16.f32 "
        "{%0,%1,%2,%3},{%4,%5,%6,%7},{%8,%9},{%0,%1,%2,%3};"
        : "+f"(c[0]), "+f"(c[1]), "+f"(c[2]), "+f"(c[3])
        : "r"(a[0]), "r"(a[1]), "r"(a[2]), "r"(a[3]), "r"(b0), "r"(b1));
}
// ldmatrix x4: four 8x8 fp16 tiles
__device__ __forceinline__ void ldsm4(unsigned* r, unsigned saddr) {
    asm volatile("ldmatrix.sync.aligned.m8n8.x4.shared.b16 {%0,%1,%2,%3}, [%4];"
        : "=r"(r[0]), "=r"(r[1]), "=r"(r[2]), "=r"(r[3]) : "r"(saddr));
}
// v = hi + lo/1024 ; lo stored pre-scaled so it stays in fp16 normal range
__device__ __forceinline__ void split_store_h(float v, __half* hi, __half* lo) {
    __half h = __float2half_rn(v);
    *hi = h;
    *lo = __float2half_rn((v - __half2float(h)) * 1024.0f);
}

// ---------------- init: h=0, c=0 (and splits), V[w][b][:] = bv --------------
__global__ void init_kernel(const float* __restrict__ bv) {
    int idx = blockIdx.x * blockDim.x + threadIdx.x;
    int stride = gridDim.x * blockDim.x;
    __half z = __float2half(0.f);
    for (int i = idx; i < B_DIM * H_DIM; i += stride) {
        g_h_hi[0][i] = z; g_h_lo[0][i] = z;
        g_c[i] = 0.f; g_c_hi[i] = z; g_c_lo[i] = z;
    }
    for (int i = idx; i < W_WIN * B_DIM * H_DIM; i += stride) {
        g_V[i] = bv[i % H_DIM];
    }
}

// ---------------- prep kernels ----------------------------------------------
__global__ void prep_x(const float* __restrict__ x) {
    long total = (long)T_LEN * B_DIM * I_DIM;
    long stride = (long)gridDim.x * blockDim.x;
    for (long i = (long)blockIdx.x * blockDim.x + threadIdx.x; i < total; i += stride) {
        split_store_h(x[i], &g_x_hi[i], &g_x_lo[i]);
    }
}
__global__ void prep_wc(const float* __restrict__ Wi,
                        const float* __restrict__ Wh,
                        const float* __restrict__ Wa) {
    long total = (long)G4H * KC_K;
    long stride = (long)gridDim.x * blockDim.x;
    for (long i = (long)blockIdx.x * blockDim.x + threadIdx.x; i < total; i += stride) {
        int n = (int)(i / KC_K), k = (int)(i % KC_K);
        float w;
        if (k < I_DIM)   w = Wi[(size_t)k * G4H + n];
        else if (k < IH) w = Wh[(size_t)(k - I_DIM) * G4H + n];
        else             w = Wa[(size_t)(k - IH) * G4H + n];
        split_store_h(w, &g_Wc_hi[i], &g_Wc_lo[i]);
    }
}
__global__ void prep_wqv(const float* __restrict__ Wq,
                         const float* __restrict__ Wv) {
    long totq = (long)H_DIM * IH;
    long totv = (long)H_DIM * H_DIM;
    long stride = (long)gridDim.x * blockDim.x;
    for (long i = (long)blockIdx.x * blockDim.x + threadIdx.x; i < totq + totv; i += stride) {
        if (i < totq) {
            int n = (int)(i / IH), k = (int)(i % IH);
            split_store_h(Wq[(size_t)k * H_DIM + n], &g_Wq_hi[i], &g_Wq_lo[i]);
        } else {
            long j = i - totq;
            int n = (int)(j / H_DIM), k = (int)(j % H_DIM);
            split_store_h(Wv[(size_t)k * H_DIM + n], &g_Wv_hi[j], &g_Wv_lo[j]);
        }
    }
}

// ---------------- KA: Q = [x_t|h] @ Wq + bq   AND   V[t%W] = c @ Wv + bv ----
// grid = 128 blocks x 128 threads (4 warps, 2x2 m16n16 each).
__global__ __launch_bounds__(128) void ka_kernel(
    int t, const float* __restrict__ bq, const float* __restrict__ bv)
{
    __shared__ __align__(16) __half Ah[2][32][40], Al[2][32][40];
    __shared__ __align__(16) __half Bh[2][32][40], Bl[2][32][40];

    const int blk = blockIdx.x;
    const bool isQ = (blk < 64);
    const int bid = blk & 63;
    const int m0 = (bid >> 4) * 32;     // 4 M-tiles
    const int n0 = (bid & 15) * 32;     // 16 N-tiles

    const __half* __restrict__ xhi = g_x_hi + (size_t)t * B_DIM * I_DIM;
    const __half* __restrict__ xlo = g_x_lo + (size_t)t * B_DIM * I_DIM;
    const __half* __restrict__ hhi = g_h_hi[t & 1];
    const __half* __restrict__ hlo = g_h_lo[t & 1];
    const __half* __restrict__ WH  = isQ ? g_Wq_hi : g_Wv_hi;
    const __half* __restrict__ WL  = isQ ? g_Wq_lo : g_Wv_lo;
    const int Ktot = isQ ? IH : H_DIM;
    const int nt   = Ktot / 32;

    const int tid  = threadIdx.x;
    const int lane = tid & 31;
    const int warp = tid >> 5;
    const int mrow = (warp & 1) * 16;
    const int ncol = (warp >> 1) * 16;
    const int g    = lane >> 2, tg = lane & 3;

    // ldmatrix lane addressing
    const int a_r = mrow + (lane & 7) + ((lane >> 3) & 1) * 8;
    const int a_k = (lane >> 4) * 8;
    const int b_r = ncol + (lane & 7) + (lane >> 4) * 8;
    const int b_k = ((lane >> 3) & 1) * 8;

    const int ar  = tid >> 2;            // 0..31 row (stage loads)
    const int ac8 = (tid & 3) * 8;

    auto issue = [&](int it, int s) {
        const int kk = it * 32;
        {
            const __half *ph, *pl;
            if (isQ) {
                int gk = kk + ac8;
                if (gk < I_DIM) {
                    ph = xhi + (size_t)(m0 + ar) * I_DIM + gk;
                    pl = xlo + (size_t)(m0 + ar) * I_DIM + gk;
                } else {
                    ph = hhi + (size_t)(m0 + ar) * H_DIM + (gk - I_DIM);
                    pl = hlo + (size_t)(m0 + ar) * H_DIM + (gk - I_DIM);
                }
            } else {
                ph = g_c_hi + (size_t)(m0 + ar) * H_DIM + kk + ac8;
                pl = g_c_lo + (size_t)(m0 + ar) * H_DIM + kk + ac8;
            }
            cp16(&Ah[s][ar][ac8], ph);
            cp16(&Al[s][ar][ac8], pl);
        }
        {
            size_t off = (size_t)(n0 + ar) * Ktot + kk + ac8;
            cp16(&Bh[s][ar][ac8], WH + off);
            cp16(&Bl[s][ar][ac8], WL + off);
        }
        cp_commit();
    };

    float cHH[2][4] = {}, cLH[2][4] = {}, cHL[2][4] = {};

    issue(0, 0);
    for (int it = 0; it < nt; it++) {
        const int s = it & 1;
        if (it + 1 < nt) { issue(it + 1, s ^ 1); cp_wait1(); }
        else             { cp_wait0(); }
        __syncthreads();

        #pragma unroll
        for (int ko = 0; ko < 32; ko += 16) {
            unsigned ah[4], al[4], bbh[4], bbl[4];
            ldsm4(ah,  smem_u32(&Ah[s][a_r][ko + a_k]));
            ldsm4(al,  smem_u32(&Al[s][a_r][ko + a_k]));
            ldsm4(bbh, smem_u32(&Bh[s][b_r][ko + b_k]));
            ldsm4(bbl, smem_u32(&Bl[s][b_r][ko + b_k]));
            hmma(cHH[0], ah, bbh[0], bbh[1]);
            hmma(cHH[1], ah, bbh[2], bbh[3]);
            hmma(cLH[0], al, bbh[0], bbh[1]);
            hmma(cLH[1], al, bbh[2], bbh[3]);
            hmma(cHL[0], ah, bbl[0], bbl[1]);
            hmma(cHL[1], ah, bbl[2], bbl[3]);
        }
        __syncthreads();
    }

    const float* bias = isQ ? bq : bv;
    float* outp = isQ ? g_Q : (g_V + (size_t)(t % W_WIN) * B_DIM * H_DIM);
    #pragma unroll
    for (int ns = 0; ns < 2; ns++) {
        float a0 = cHH[ns][0] + (cLH[ns][0] + cHL[ns][0]) * INV1024;
        float a1 = cHH[ns][1] + (cLH[ns][1] + cHL[ns][1]) * INV1024;
        float a2 = cHH[ns][2] + (cLH[ns][2] + cHL[ns][2]) * INV1024;
        float a3 = cHH[ns][3] + (cLH[ns][3] + cHL[ns][3]) * INV1024;
        int col = n0 + ncol + ns * 8 + 2 * tg;
        int r0 = m0 + mrow + g, r1 = r0 + 8;
        outp[(size_t)r0 * H_DIM + col]     = a0 + bias[col];
        outp[(size_t)r0 * H_DIM + col + 1] = a1 + bias[col + 1];
        outp[(size_t)r1 * H_DIM + col]     = a2 + bias[col];
        outp[(size_t)r1 * H_DIM + col + 1] = a3 + bias[col + 1];
    }
}

// ---------------- KB: scores -> softmax -> attn (writes attn splits) --------
__global__ __launch_bounds__(128) void kb_kernel(int t) {
    const float inv_sqrt_dk = 0.044194173824159216f; // 1/sqrt(512)
    int b = blockIdx.x;
    int tid = threadIdx.x;
    __shared__ float sQ[H_DIM];
    __shared__ float sS[W_WIN];
    __shared__ float sP[W_WIN];

    for (int j = tid; j < H_DIM; j += 128) sQ[j] = g_Q[(size_t)b * H_DIM + j];
    __syncthreads();

    int nv = (t + 1 < W_WIN) ? (t + 1) : W_WIN;
    int warp = tid / 32, lane = tid % 32;
    for (int w = warp; w < nv; w += 4) {
        const float* Vp = g_V + (size_t)(w * B_DIM + b) * H_DIM;
        float p = 0.f;
        for (int j = lane; j < H_DIM; j += 32) p += sQ[j] * Vp[j];
        #pragma unroll
        for (int o = 16; o > 0; o >>= 1) p += __shfl_xor_sync(0xffffffffu, p, o);
        if (lane == 0) sS[w] = p * inv_sqrt_dk;
    }
    __syncthreads();
    if (tid == 0) {
        float m = sS[0];
        for (int w = 1; w < nv; w++) m = fmaxf(m, sS[w]);
        float sum = 0.f;
        for (int w = 0; w < nv; w++) { float e = expf(sS[w] - m); sP[w] = e; sum += e; }
        float inv = 1.f / sum;
        for (int w = 0; w < nv; w++) sP[w] *= inv;
    }
    __syncthreads();
    for (int j = tid; j < H_DIM; j += 128) {
        float a = 0.f;
        for (int w = 0; w < nv; w++)
            a += sP[w] * g_V[(size_t)(w * B_DIM + b) * H_DIM + j];
        size_t idx = (size_t)b * H_DIM + j;
        split_store_h(a, &g_attn_hi[idx], &g_attn_lo[idx]);
    }
}

// ---------------- KC: fused cell GEMM (fp16 mma) + LSTM pointwise -----------
// grid = 256 blocks (4 M-tiles x 64 j-tiles) x 128 threads.
// Tile: M=32 x N=32 (4 gates x 8 j). Warp 2x2: m16 x n16.
__global__ __launch_bounds__(128) void kc_kernel(
    int t,
    const float* __restrict__ bi, const float* __restrict__ ba,
    float* __restrict__ out)
{
    __shared__ __align__(16) __half Ah[2][32][40], Al[2][32][40];
    __shared__ __align__(16) __half Bh[2][32][40], Bl[2][32][40];
    __shared__ float sP[32][33];

    const int m0 = (blockIdx.x >> 6) * 32;  // 4 M-tiles
    const int j0 = (blockIdx.x & 63) * 8;   // 64 j-tiles

    const __half* __restrict__ xhi = g_x_hi + (size_t)t * B_DIM * I_DIM;
    const __half* __restrict__ xlo = g_x_lo + (size_t)t * B_DIM * I_DIM;
    const __half* __restrict__ hhi = g_h_hi[t & 1];
    const __half* __restrict__ hlo = g_h_lo[t & 1];
    __half* __restrict__ hohi = g_h_hi[(t + 1) & 1];
    __half* __restrict__ holo = g_h_lo[(t + 1) & 1];

    const int tid  = threadIdx.x;
    const int lane = tid & 31;
    const int warp = tid >> 5;
    const int mrow = (warp & 1) * 16;
    const int ncol = (warp >> 1) * 16;
    const int g    = lane >> 2, tg = lane & 3;

    const int a_r = mrow + (lane & 7) + ((lane >> 3) & 1) * 8;
    const int a_k = (lane >> 4) * 8;
    const int b_r = ncol + (lane & 7) + (lane >> 4) * 8;
    const int b_k = ((lane >> 3) & 1) * 8;

    const int ar  = tid >> 2;
    const int ac8 = (tid & 3) * 8;

    auto issue = [&](int it, int s) {
        const int kk = it * 32;
        const __half *Shi, *Slo; int ldA, koff;
        if (kk < I_DIM)   { Shi = xhi;       Slo = xlo;       ldA = I_DIM; koff = kk; }
        else if (kk < IH) { Shi = hhi;       Slo = hlo;       ldA = H_DIM; koff = kk - I_DIM; }
        else              { Shi = g_attn_hi; Slo = g_attn_lo; ldA = H_DIM; koff = kk - IH; }
        cp16(&Ah[s][ar][ac8], Shi + (size_t)(m0 + ar) * ldA + koff + ac8);
        cp16(&Al[s][ar][ac8], Slo + (size_t)(m0 + ar) * ldA + koff + ac8);
        {
            int gn = (ar >> 3) * H_DIM + j0 + (ar & 7);
            size_t off = (size_t)gn * KC_K + kk + ac8;
            cp16(&Bh[s][ar][ac8], g_Wc_hi + off);
            cp16(&Bl[s][ar][ac8], g_Wc_lo + off);
        }
        cp_commit();
    };

    float cHH[2][4] = {}, cLH[2][4] = {}, cHL[2][4] = {};

    const int nt = KC_K / 32;  // 36
    issue(0, 0);
    for (int it = 0; it < nt; it++) {
        const int s = it & 1;
        if (it + 1 < nt) { issue(it + 1, s ^ 1); cp_wait1(); }
        else             { cp_wait0(); }
        __syncthreads();

        #pragma unroll
        for (int ko = 0; ko < 32; ko += 16) {
            unsigned ah[4], al[4], bbh[4], bbl[4];
            ldsm4(ah,  smem_u32(&Ah[s][a_r][ko + a_k]));
            ldsm4(al,  smem_u32(&Al[s][a_r][ko + a_k]));
            ldsm4(bbh, smem_u32(&Bh[s][b_r][ko + b_k]));
            ldsm4(bbl, smem_u32(&Bl[s][b_r][ko + b_k]));
            hmma(cHH[0], ah, bbh[0], bbh[1]);
            hmma(cHH[1], ah, bbh[2], bbh[3]);
            hmma(cLH[0], al, bbh[0], bbh[1]);
            hmma(cLH[1], al, bbh[2], bbh[3]);
            hmma(cHL[0], ah, bbl[0], bbl[1]);
            hmma(cHL[1], ah, bbl[2], bbl[3]);
        }
        __syncthreads();
    }

    // combine chains + exchange preact through smem
    #pragma unroll
    for (int ns = 0; ns < 2; ns++) {
        int col0 = ncol + ns * 8 + 2 * tg;
        sP[mrow + g][col0]         = cHH[ns][0] + (cLH[ns][0] + cHL[ns][0]) * INV1024;
        sP[mrow + g][col0 + 1]     = cHH[ns][1] + (cLH[ns][1] + cHL[ns][1]) * INV1024;
        sP[mrow + g + 8][col0]     = cHH[ns][2] + (cLH[ns][2] + cHL[ns][2]) * INV1024;
        sP[mrow + g + 8][col0 + 1] = cHH[ns][3] + (cLH[ns][3] + cHL[ns][3]) * INV1024;
    }
    __syncthreads();

    const int row = tid >> 3;          // 0..15
    const int jj  = tid & 7;           // 0..7
    const int j   = j0 + jj;

    float bii = bi[j]             + ba[j];
    float bif = bi[H_DIM + j]     + ba[H_DIM + j];
    float bio = bi[2 * H_DIM + j] + ba[2 * H_DIM + j];
    float big = bi[3 * H_DIM + j] + ba[3 * H_DIM + j];

    #pragma unroll
    for (int half = 0; half < 2; half++) {
        int r = row + half * 16;
        int b = m0 + r;
        float pi = sP[r][jj]      + bii;
        float pf = sP[r][8 + jj]  + bif;
        float po = sP[r][16 + jj] + bio;
        float pg = sP[r][24 + jj] + big;

        float ig = 1.f / (1.f + expf(-pi));
        float fg = 1.f / (1.f + expf(-pf));
        float og = 1.f / (1.f + expf(-po));
        float gg = tanhf(pg);

        size_t idx = (size_t)b * H_DIM + j;
        float cn = g_c[idx] * fg + ig * gg;
        float hn = og * tanhf(cn);

        g_c[idx] = cn;
        split_store_h(cn, &g_c_hi[idx], &g_c_lo[idx]);
        split_store_h(hn, &hohi[idx], &holo[idx]);
        out[(size_t)t * B_DIM * H_DIM + idx] = hn;
    }
}

// ---------------- launcher --------------------------------------------------
extern "C" void kernel_launch(void* const* d_in, const int* in_sizes, int n_in,
                              void* d_out, int out_size) {
    const float* x  = (const float*)d_in[0];
    const float* Wi = (const float*)d_in[1];
    const float* bi = (const float*)d_in[2];
    const float* Wh = (const float*)d_in[3];
    const float* Wv = (const float*)d_in[4];
    const float* bv = (const float*)d_in[5];
    const float* Wq = (const float*)d_in[6];
    const float* bq = (const float*)d_in[7];
    const float* Wa = (const float*)d_in[8];
    const float* ba = (const float*)d_in[9];
    float* out = (float*)d_out;

    init_kernel<<<1024, 256>>>(bv);
    prep_x<<<2048, 256>>>(x);
    prep_wc<<<2048, 256>>>(Wi, Wh, Wa);
    prep_wqv<<<1024, 256>>>(Wq, Wv);
    for (int t = 0; t < T_LEN; t++) {
        ka_kernel<<<128, 128>>>(t, bq, bv);
        kb_kernel<<<128, 128>>>(t);
        kc_kernel<<<256, 128>>>(t, bi, ba, out);
    }
}

// round 14
// speedup vs baseline: 1.7889x; 1.2135x over previous
#include <cuda_runtime.h>
#include <cuda_fp16.h>
#include <math.h>

#define T_LEN 128
#define B_DIM 128
#define I_DIM 128
#define H_DIM 512
#define W_WIN 16
#define G4H   2048   // 4*H
#define IH    640    // I+H
#define KC_K  1152   // I + H + H (virtual K for cell GEMM)
#define INV1024 0.0009765625f

// ---------------- scratch (device globals; no allocation allowed) ----------
__device__ float g_c[B_DIM * H_DIM];               // cell state fp32 master
__device__ float g_V[W_WIN * B_DIM * H_DIM];       // V cache fp32
__device__ float g_Q[B_DIM * H_DIM];               // Q fp32

// fp16-split activations (hi, lo*1024), maintained by epilogues
__device__ __half g_h_hi[2][B_DIM * H_DIM];
__device__ __half g_h_lo[2][B_DIM * H_DIM];
__device__ __half g_c_hi[B_DIM * H_DIM];
__device__ __half g_c_lo[B_DIM * H_DIM];
__device__ __half g_attn_hi[B_DIM * H_DIM];
__device__ __half g_attn_lo[B_DIM * H_DIM];
__device__ __half g_x_hi[T_LEN * B_DIM * I_DIM];
__device__ __half g_x_lo[T_LEN * B_DIM * I_DIM];

// transposed + fp16-split weights (computed once per call), [n][k]
__device__ __half g_Wc_hi[G4H * KC_K];
__device__ __half g_Wc_lo[G4H * KC_K];
__device__ __half g_Wq_hi[H_DIM * IH];
__device__ __half g_Wq_lo[H_DIM * IH];
__device__ __half g_Wv_hi[H_DIM * H_DIM];
__device__ __half g_Wv_lo[H_DIM * H_DIM];

// ---------------- helpers ---------------------------------------------------
__device__ __forceinline__ unsigned smem_u32(const void* p) {
    return (unsigned)__cvta_generic_to_shared(p);
}
__device__ __forceinline__ void cp16(void* dst, const void* src) {
    asm volatile("cp.async.cg.shared.global [%0], [%1], 16;\n"
                 :: "r"(smem_u32(dst)), "l"(src));
}
__device__ __forceinline__ void cp_commit() {
    asm volatile("cp.async.commit_group;\n" ::: "memory");
}
__device__ __forceinline__ void cp_wait1() {
    asm volatile("cp.async.wait_group 1;\n" ::: "memory");
}
__device__ __forceinline__ void cp_wait0() {
    asm volatile("cp.async.wait_group 0;\n" ::: "memory");
}
// D += A(m16k16,row) * B(k16n8,col)   fp16 in, fp32 accum
__device__ __forceinline__ void hmma(float* c, const unsigned* a,
                                     unsigned b0, unsigned b1) {
    asm("mma.sync.aligned.m16n8k16.row.col.f32.f16.f16.f32 "
        "{%0,%1,%2,%3},{%4,%5,%6,%7},{%8,%9},{%0,%1,%2,%3};"
        : "+f"(c[0]), "+f"(c[1]), "+f"(c[2]), "+f"(c[3])
        : "r"(a[0]), "r"(a[1]), "r"(a[2]), "r"(a[3]), "r"(b0), "r"(b1));
}
// ldmatrix x4: four 8x8 fp16 tiles
__device__ __forceinline__ void ldsm4(unsigned* r, unsigned saddr) {
    asm volatile("ldmatrix.sync.aligned.m8n8.x4.shared.b16 {%0,%1,%2,%3}, [%4];"
        : "=r"(r[0]), "=r"(r[1]), "=r"(r[2]), "=r"(r[3]) : "r"(saddr));
}
// v = hi + lo/1024 ; lo stored pre-scaled so it stays in fp16 normal range
__device__ __forceinline__ void split_store_h(float v, __half* hi, __half* lo) {
    __half h = __float2half_rn(v);
    *hi = h;
    *lo = __float2half_rn((v - __half2float(h)) * 1024.0f);
}

// ---------------- init: h=0, c=0 (and splits), V[w][b][:] = bv --------------
__global__ void init_kernel(const float* __restrict__ bv) {
    int idx = blockIdx.x * blockDim.x + threadIdx.x;
    int stride = gridDim.x * blockDim.x;
    __half z = __float2half(0.f);
    for (int i = idx; i < B_DIM * H_DIM; i += stride) {
        g_h_hi[0][i] = z; g_h_lo[0][i] = z;
        g_c[i] = 0.f; g_c_hi[i] = z; g_c_lo[i] = z;
    }
    for (int i = idx; i < W_WIN * B_DIM * H_DIM; i += stride) {
        g_V[i] = bv[i % H_DIM];
    }
}

// ---------------- prep kernels ----------------------------------------------
__global__ void prep_x(const float* __restrict__ x) {
    long total = (long)T_LEN * B_DIM * I_DIM;
    long stride = (long)gridDim.x * blockDim.x;
    for (long i = (long)blockIdx.x * blockDim.x + threadIdx.x; i < total; i += stride) {
        split_store_h(x[i], &g_x_hi[i], &g_x_lo[i]);
    }
}
__global__ void prep_wc(const float* __restrict__ Wi,
                        const float* __restrict__ Wh,
                        const float* __restrict__ Wa) {
    long total = (long)G4H * KC_K;
    long stride = (long)gridDim.x * blockDim.x;
    for (long i = (long)blockIdx.x * blockDim.x + threadIdx.x; i < total; i += stride) {
        int n = (int)(i / KC_K), k = (int)(i % KC_K);
        float w;
        if (k < I_DIM)   w = Wi[(size_t)k * G4H + n];
        else if (k < IH) w = Wh[(size_t)(k - I_DIM) * G4H + n];
        else             w = Wa[(size_t)(k - IH) * G4H + n];
        split_store_h(w, &g_Wc_hi[i], &g_Wc_lo[i]);
    }
}
__global__ void prep_wqv(const float* __restrict__ Wq,
                         const float* __restrict__ Wv) {
    long totq = (long)H_DIM * IH;
    long totv = (long)H_DIM * H_DIM;
    long stride = (long)gridDim.x * blockDim.x;
    for (long i = (long)blockIdx.x * blockDim.x + threadIdx.x; i < totq + totv; i += stride) {
        if (i < totq) {
            int n = (int)(i / IH), k = (int)(i % IH);
            split_store_h(Wq[(size_t)k * H_DIM + n], &g_Wq_hi[i], &g_Wq_lo[i]);
        } else {
            long j = i - totq;
            int n = (int)(j / H_DIM), k = (int)(j % H_DIM);
            split_store_h(Wv[(size_t)k * H_DIM + n], &g_Wv_hi[j], &g_Wv_lo[j]);
        }
    }
}

// ---------------- KA: Q = [x_t|h] @ Wq + bq   AND   V[t%W] = c @ Wv + bv ----
// grid = 128 blocks x 128 threads (4 warps, 2x2 m16n16 each). TK=64.
__global__ __launch_bounds__(128) void ka_kernel(
    int t, const float* __restrict__ bq, const float* __restrict__ bv)
{
    __shared__ __align__(16) __half Ah[2][32][72], Al[2][32][72];
    __shared__ __align__(16) __half Bh[2][32][72], Bl[2][32][72];

    const int blk = blockIdx.x;
    const bool isQ = (blk < 64);
    const int bid = blk & 63;
    const int m0 = (bid >> 4) * 32;     // 4 M-tiles
    const int n0 = (bid & 15) * 32;     // 16 N-tiles

    const __half* __restrict__ xhi = g_x_hi + (size_t)t * B_DIM * I_DIM;
    const __half* __restrict__ xlo = g_x_lo + (size_t)t * B_DIM * I_DIM;
    const __half* __restrict__ hhi = g_h_hi[t & 1];
    const __half* __restrict__ hlo = g_h_lo[t & 1];
    const __half* __restrict__ WH  = isQ ? g_Wq_hi : g_Wv_hi;
    const __half* __restrict__ WL  = isQ ? g_Wq_lo : g_Wv_lo;
    const int Ktot = isQ ? IH : H_DIM;
    const int nt   = Ktot / 64;          // 10 or 8

    const int tid  = threadIdx.x;
    const int lane = tid & 31;
    const int warp = tid >> 5;
    const int mrow = (warp & 1) * 16;
    const int ncol = (warp >> 1) * 16;
    const int g    = lane >> 2, tg = lane & 3;

    // ldmatrix lane addressing
    const int a_r = mrow + (lane & 7) + ((lane >> 3) & 1) * 8;
    const int a_k = (lane >> 4) * 8;
    const int b_r = ncol + (lane & 7) + (lane >> 4) * 8;
    const int b_k = ((lane >> 3) & 1) * 8;

    auto issue = [&](int it, int s) {
        const int kk = it * 64;
        // A hi/lo: 32 rows x 64 halves -> 2 cp16/thread per plane
        #pragma unroll
        for (int l = 0; l < 2; l++) {
            int id = tid + l * 128;
            int r = id >> 3, c8 = (id & 7) * 8;
            const __half *ph, *pl;
            if (isQ) {
                int gk = kk + c8;
                if (gk < I_DIM) {
                    ph = xhi + (size_t)(m0 + r) * I_DIM + gk;
                    pl = xlo + (size_t)(m0 + r) * I_DIM + gk;
                } else {
                    ph = hhi + (size_t)(m0 + r) * H_DIM + (gk - I_DIM);
                    pl = hlo + (size_t)(m0 + r) * H_DIM + (gk - I_DIM);
                }
            } else {
                ph = g_c_hi + (size_t)(m0 + r) * H_DIM + kk + c8;
                pl = g_c_lo + (size_t)(m0 + r) * H_DIM + kk + c8;
            }
            cp16(&Ah[s][r][c8], ph);
            cp16(&Al[s][r][c8], pl);
        }
        // B hi/lo
        #pragma unroll
        for (int l = 0; l < 2; l++) {
            int id = tid + l * 128;
            int r = id >> 3, c8 = (id & 7) * 8;
            size_t off = (size_t)(n0 + r) * Ktot + kk + c8;
            cp16(&Bh[s][r][c8], WH + off);
            cp16(&Bl[s][r][c8], WL + off);
        }
        cp_commit();
    };

    float cHH[2][4] = {}, cLH[2][4] = {}, cHL[2][4] = {};

    issue(0, 0);
    for (int it = 0; it < nt; it++) {
        const int s = it & 1;
        if (it + 1 < nt) { issue(it + 1, s ^ 1); cp_wait1(); }
        else             { cp_wait0(); }
        __syncthreads();

        #pragma unroll
        for (int ko = 0; ko < 64; ko += 16) {
            unsigned ah[4], al[4], bbh[4], bbl[4];
            ldsm4(ah,  smem_u32(&Ah[s][a_r][ko + a_k]));
            ldsm4(al,  smem_u32(&Al[s][a_r][ko + a_k]));
            ldsm4(bbh, smem_u32(&Bh[s][b_r][ko + b_k]));
            ldsm4(bbl, smem_u32(&Bl[s][b_r][ko + b_k]));
            hmma(cHH[0], ah, bbh[0], bbh[1]);
            hmma(cHH[1], ah, bbh[2], bbh[3]);
            hmma(cLH[0], al, bbh[0], bbh[1]);
            hmma(cLH[1], al, bbh[2], bbh[3]);
            hmma(cHL[0], ah, bbl[0], bbl[1]);
            hmma(cHL[1], ah, bbl[2], bbl[3]);
        }
        __syncthreads();
    }

    const float* bias = isQ ? bq : bv;
    float* outp = isQ ? g_Q : (g_V + (size_t)(t % W_WIN) * B_DIM * H_DIM);
    #pragma unroll
    for (int ns = 0; ns < 2; ns++) {
        float a0 = cHH[ns][0] + (cLH[ns][0] + cHL[ns][0]) * INV1024;
        float a1 = cHH[ns][1] + (cLH[ns][1] + cHL[ns][1]) * INV1024;
        float a2 = cHH[ns][2] + (cLH[ns][2] + cHL[ns][2]) * INV1024;
        float a3 = cHH[ns][3] + (cLH[ns][3] + cHL[ns][3]) * INV1024;
        int col = n0 + ncol + ns * 8 + 2 * tg;
        int r0 = m0 + mrow + g, r1 = r0 + 8;
        outp[(size_t)r0 * H_DIM + col]     = a0 + bias[col];
        outp[(size_t)r0 * H_DIM + col + 1] = a1 + bias[col + 1];
        outp[(size_t)r1 * H_DIM + col]     = a2 + bias[col];
        outp[(size_t)r1 * H_DIM + col + 1] = a3 + bias[col + 1];
    }
}

// ---------------- KB: scores -> softmax -> attn (writes attn splits) --------
__global__ __launch_bounds__(128) void kb_kernel(int t) {
    const float inv_sqrt_dk = 0.044194173824159216f; // 1/sqrt(512)
    int b = blockIdx.x;
    int tid = threadIdx.x;
    __shared__ float sQ[H_DIM];
    __shared__ float sS[W_WIN];
    __shared__ float sP[W_WIN];

    for (int j = tid; j < H_DIM; j += 128) sQ[j] = g_Q[(size_t)b * H_DIM + j];
    __syncthreads();

    int nv = (t + 1 < W_WIN) ? (t + 1) : W_WIN;
    int warp = tid / 32, lane = tid % 32;
    for (int w = warp; w < nv; w += 4) {
        const float* Vp = g_V + (size_t)(w * B_DIM + b) * H_DIM;
        float p = 0.f;
        for (int j = lane; j < H_DIM; j += 32) p += sQ[j] * Vp[j];
        #pragma unroll
        for (int o = 16; o > 0; o >>= 1) p += __shfl_xor_sync(0xffffffffu, p, o);
        if (lane == 0) sS[w] = p * inv_sqrt_dk;
    }
    __syncthreads();
    if (tid == 0) {
        float m = sS[0];
        for (int w = 1; w < nv; w++) m = fmaxf(m, sS[w]);
        float sum = 0.f;
        for (int w = 0; w < nv; w++) { float e = expf(sS[w] - m); sP[w] = e; sum += e; }
        float inv = 1.f / sum;
        for (int w = 0; w < nv; w++) sP[w] *= inv;
    }
    __syncthreads();
    for (int j = tid; j < H_DIM; j += 128) {
        float a = 0.f;
        for (int w = 0; w < nv; w++)
            a += sP[w] * g_V[(size_t)(w * B_DIM + b) * H_DIM + j];
        size_t idx = (size_t)b * H_DIM + j;
        split_store_h(a, &g_attn_hi[idx], &g_attn_lo[idx]);
    }
}

// ---------------- KC: fused cell GEMM (fp16 mma) + LSTM pointwise -----------
// grid = 256 blocks (4 M-tiles x 64 j-tiles) x 128 threads. TK=64.
// Tile: M=32 x N=32 (4 gates x 8 j). Warp 2x2: m16 x n16.
__global__ __launch_bounds__(128) void kc_kernel(
    int t,
    const float* __restrict__ bi, const float* __restrict__ ba,
    float* __restrict__ out)
{
    __shared__ __align__(16) __half Ah[2][32][72], Al[2][32][72];
    __shared__ __align__(16) __half Bh[2][32][72], Bl[2][32][72];
    __shared__ float sP[32][33];

    const int m0 = (blockIdx.x >> 6) * 32;  // 4 M-tiles
    const int j0 = (blockIdx.x & 63) * 8;   // 64 j-tiles

    const __half* __restrict__ xhi = g_x_hi + (size_t)t * B_DIM * I_DIM;
    const __half* __restrict__ xlo = g_x_lo + (size_t)t * B_DIM * I_DIM;
    const __half* __restrict__ hhi = g_h_hi[t & 1];
    const __half* __restrict__ hlo = g_h_lo[t & 1];
    __half* __restrict__ hohi = g_h_hi[(t + 1) & 1];
    __half* __restrict__ holo = g_h_lo[(t + 1) & 1];

    const int tid  = threadIdx.x;
    const int lane = tid & 31;
    const int warp = tid >> 5;
    const int mrow = (warp & 1) * 16;
    const int ncol = (warp >> 1) * 16;
    const int g    = lane >> 2, tg = lane & 3;

    const int a_r = mrow + (lane & 7) + ((lane >> 3) & 1) * 8;
    const int a_k = (lane >> 4) * 8;
    const int b_r = ncol + (lane & 7) + (lane >> 4) * 8;
    const int b_k = ((lane >> 3) & 1) * 8;

    auto issue = [&](int it, int s) {
        const int kk = it * 64;
        const __half *Shi, *Slo; int ldA, koff;
        if (kk < I_DIM)   { Shi = xhi;       Slo = xlo;       ldA = I_DIM; koff = kk; }
        else if (kk < IH) { Shi = hhi;       Slo = hlo;       ldA = H_DIM; koff = kk - I_DIM; }
        else              { Shi = g_attn_hi; Slo = g_attn_lo; ldA = H_DIM; koff = kk - IH; }
        #pragma unroll
        for (int l = 0; l < 2; l++) {
            int id = tid + l * 128;
            int r = id >> 3, c8 = (id & 7) * 8;
            cp16(&Ah[s][r][c8], Shi + (size_t)(m0 + r) * ldA + koff + c8);
            cp16(&Al[s][r][c8], Slo + (size_t)(m0 + r) * ldA + koff + c8);
        }
        #pragma unroll
        for (int l = 0; l < 2; l++) {
            int id = tid + l * 128;
            int r = id >> 3, c8 = (id & 7) * 8;
            int gn = (r >> 3) * H_DIM + j0 + (r & 7);
            size_t off = (size_t)gn * KC_K + kk + c8;
            cp16(&Bh[s][r][c8], g_Wc_hi + off);
            cp16(&Bl[s][r][c8], g_Wc_lo + off);
        }
        cp_commit();
    };

    float cHH[2][4] = {}, cLH[2][4] = {}, cHL[2][4] = {};

    const int nt = KC_K / 64;  // 18
    issue(0, 0);
    for (int it = 0; it < nt; it++) {
        const int s = it & 1;
        if (it + 1 < nt) { issue(it + 1, s ^ 1); cp_wait1(); }
        else             { cp_wait0(); }
        __syncthreads();

        #pragma unroll
        for (int ko = 0; ko < 64; ko += 16) {
            unsigned ah[4], al[4], bbh[4], bbl[4];
            ldsm4(ah,  smem_u32(&Ah[s][a_r][ko + a_k]));
            ldsm4(al,  smem_u32(&Al[s][a_r][ko + a_k]));
            ldsm4(bbh, smem_u32(&Bh[s][b_r][ko + b_k]));
            ldsm4(bbl, smem_u32(&Bl[s][b_r][ko + b_k]));
            hmma(cHH[0], ah, bbh[0], bbh[1]);
            hmma(cHH[1], ah, bbh[2], bbh[3]);
            hmma(cLH[0], al, bbh[0], bbh[1]);
            hmma(cLH[1], al, bbh[2], bbh[3]);
            hmma(cHL[0], ah, bbl[0], bbl[1]);
            hmma(cHL[1], ah, bbl[2], bbl[3]);
        }
        __syncthreads();
    }

    // combine chains + exchange preact through smem
    #pragma unroll
    for (int ns = 0; ns < 2; ns++) {
        int col0 = ncol + ns * 8 + 2 * tg;
        sP[mrow + g][col0]         = cHH[ns][0] + (cLH[ns][0] + cHL[ns][0]) * INV1024;
        sP[mrow + g][col0 + 1]     = cHH[ns][1] + (cLH[ns][1] + cHL[ns][1]) * INV1024;
        sP[mrow + g + 8][col0]     = cHH[ns][2] + (cLH[ns][2] + cHL[ns][2]) * INV1024;
        sP[mrow + g + 8][col0 + 1] = cHH[ns][3] + (cLH[ns][3] + cHL[ns][3]) * INV1024;
    }
    __syncthreads();

    const int row = tid >> 3;          // 0..15
    const int jj  = tid & 7;           // 0..7
    const int j   = j0 + jj;

    float bii = bi[j]             + ba[j];
    float bif = bi[H_DIM + j]     + ba[H_DIM + j];
    float bio = bi[2 * H_DIM + j] + ba[2 * H_DIM + j];
    float big = bi[3 * H_DIM + j] + ba[3 * H_DIM + j];

    #pragma unroll
    for (int half = 0; half < 2; half++) {
        int r = row + half * 16;
        int b = m0 + r;
        float pi = sP[r][jj]      + bii;
        float pf = sP[r][8 + jj]  + bif;
        float po = sP[r][16 + jj] + bio;
        float pg = sP[r][24 + jj] + big;

        float ig = 1.f / (1.f + expf(-pi));
        float fg = 1.f / (1.f + expf(-pf));
        float og = 1.f / (1.f + expf(-po));
        float gg = tanhf(pg);

        size_t idx = (size_t)b * H_DIM + j;
        float cn = g_c[idx] * fg + ig * gg;
        float hn = og * tanhf(cn);

        g_c[idx] = cn;
        split_store_h(cn, &g_c_hi[idx], &g_c_lo[idx]);
        split_store_h(hn, &hohi[idx], &holo[idx]);
        out[(size_t)t * B_DIM * H_DIM + idx] = hn;
    }
}

// ---------------- launcher --------------------------------------------------
extern "C" void kernel_launch(void* const* d_in, const int* in_sizes, int n_in,
                              void* d_out, int out_size) {
    const float* x  = (const float*)d_in[0];
    const float* Wi = (const float*)d_in[1];
    const float* bi = (const float*)d_in[2];
    const float* Wh = (const float*)d_in[3];
    const float* Wv = (const float*)d_in[4];
    const float* bv = (const float*)d_in[5];
    const float* Wq = (const float*)d_in[6];
    const float* bq = (const float*)d_in[7];
    const float* Wa = (const float*)d_in[8];
    const float* ba = (const float*)d_in[9];
    float* out = (float*)d_out;

    init_kernel<<<1024, 256>>>(bv);
    prep_x<<<2048, 256>>>(x);
    prep_wc<<<2048, 256>>>(Wi, Wh, Wa);
    prep_wqv<<<1024, 256>>>(Wq, Wv);
    for (int t = 0; t < T_LEN; t++) {
        ka_kernel<<<128, 128>>>(t, bq, bv);
        kb_kernel<<<128, 128>>>(t);
        kc_kernel<<<256, 128>>>(t, bi, ba, out);
    }
}

// round 15
// speedup vs baseline: 1.9138x; 1.0698x over previous
#include <cuda_runtime.h>
#include <cuda_fp16.h>
#include <math.h>

#define T_LEN 128
#define B_DIM 128
#define I_DIM 128
#define H_DIM 512
#define W_WIN 16
#define G4H   2048   // 4*H
#define IH    640    // I+H
#define KC_K  1152   // I + H + H (virtual K for cell GEMM)
#define INV1024 0.0009765625f

// ---------------- scratch (device globals; no allocation allowed) ----------
__device__ float g_c[B_DIM * H_DIM];               // cell state fp32 master
__device__ float g_V[W_WIN * B_DIM * H_DIM];       // V cache fp32
__device__ float g_Q[B_DIM * H_DIM];               // Q fp32
__device__ float g_pre[B_DIM * G4H];               // partial preact (x|h part)

// fp16-split activations (hi, lo*1024), maintained by epilogues
__device__ __half g_h_hi[2][B_DIM * H_DIM];
__device__ __half g_h_lo[2][B_DIM * H_DIM];
__device__ __half g_c_hi[B_DIM * H_DIM];
__device__ __half g_c_lo[B_DIM * H_DIM];
__device__ __half g_attn_hi[B_DIM * H_DIM];
__device__ __half g_attn_lo[B_DIM * H_DIM];
__device__ __half g_x_hi[T_LEN * B_DIM * I_DIM];
__device__ __half g_x_lo[T_LEN * B_DIM * I_DIM];

// transposed + fp16-split weights (computed once per call), [n][k]
__device__ __half g_Wc_hi[G4H * KC_K];
__device__ __half g_Wc_lo[G4H * KC_K];
__device__ __half g_Wq_hi[H_DIM * IH];
__device__ __half g_Wq_lo[H_DIM * IH];
__device__ __half g_Wv_hi[H_DIM * H_DIM];
__device__ __half g_Wv_lo[H_DIM * H_DIM];

// ---------------- helpers ---------------------------------------------------
__device__ __forceinline__ unsigned smem_u32(const void* p) {
    return (unsigned)__cvta_generic_to_shared(p);
}
__device__ __forceinline__ void cp16(void* dst, const void* src) {
    asm volatile("cp.async.cg.shared.global [%0], [%1], 16;\n"
                 :: "r"(smem_u32(dst)), "l"(src));
}
__device__ __forceinline__ void cp_commit() {
    asm volatile("cp.async.commit_group;\n" ::: "memory");
}
__device__ __forceinline__ void cp_wait1() {
    asm volatile("cp.async.wait_group 1;\n" ::: "memory");
}
__device__ __forceinline__ void cp_wait0() {
    asm volatile("cp.async.wait_group 0;\n" ::: "memory");
}
// D += A(m16k16,row) * B(k16n8,col)   fp16 in, fp32 accum
__device__ __forceinline__ void hmma(float* c, const unsigned* a,
                                     unsigned b0, unsigned b1) {
    asm("mma.sync.aligned.m16n8k16.row.col.f32.f16.f16.f32 "
        "{%0,%1,%2,%3},{%4,%5,%6,%7},{%8,%9},{%0,%1,%2,%3};"
        : "+f"(c[0]), "+f"(c[1]), "+f"(c[2]), "+f"(c[3])
        : "r"(a[0]), "r"(a[1]), "r"(a[2]), "r"(a[3]), "r"(b0), "r"(b1));
}
// ldmatrix x4: four 8x8 fp16 tiles
__device__ __forceinline__ void ldsm4(unsigned* r, unsigned saddr) {
    asm volatile("ldmatrix.sync.aligned.m8n8.x4.shared.b16 {%0,%1,%2,%3}, [%4];"
        : "=r"(r[0]), "=r"(r[1]), "=r"(r[2]), "=r"(r[3]) : "r"(saddr));
}
// v = hi + lo/1024 ; lo stored pre-scaled so it stays in fp16 normal range
__device__ __forceinline__ void split_store_h(float v, __half* hi, __half* lo) {
    __half h = __float2half_rn(v);
    *hi = h;
    *lo = __float2half_rn((v - __half2float(h)) * 1024.0f);
}

// ---------------- init: h=0, c=0 (and splits), V[w][b][:] = bv --------------
__global__ void init_kernel(const float* __restrict__ bv) {
    int idx = blockIdx.x * blockDim.x + threadIdx.x;
    int stride = gridDim.x * blockDim.x;
    __half z = __float2half(0.f);
    for (int i = idx; i < B_DIM * H_DIM; i += stride) {
        g_h_hi[0][i] = z; g_h_lo[0][i] = z;
        g_c[i] = 0.f; g_c_hi[i] = z; g_c_lo[i] = z;
    }
    for (int i = idx; i < W_WIN * B_DIM * H_DIM; i += stride) {
        g_V[i] = bv[i % H_DIM];
    }
}

// ---------------- prep kernels ----------------------------------------------
__global__ void prep_x(const float* __restrict__ x) {
    long total = (long)T_LEN * B_DIM * I_DIM;
    long stride = (long)gridDim.x * blockDim.x;
    for (long i = (long)blockIdx.x * blockDim.x + threadIdx.x; i < total; i += stride) {
        split_store_h(x[i], &g_x_hi[i], &g_x_lo[i]);
    }
}
__global__ void prep_wc(const float* __restrict__ Wi,
                        const float* __restrict__ Wh,
                        const float* __restrict__ Wa) {
    long total = (long)G4H * KC_K;
    long stride = (long)gridDim.x * blockDim.x;
    for (long i = (long)blockIdx.x * blockDim.x + threadIdx.x; i < total; i += stride) {
        int n = (int)(i / KC_K), k = (int)(i % KC_K);
        float w;
        if (k < I_DIM)   w = Wi[(size_t)k * G4H + n];
        else if (k < IH) w = Wh[(size_t)(k - I_DIM) * G4H + n];
        else             w = Wa[(size_t)(k - IH) * G4H + n];
        split_store_h(w, &g_Wc_hi[i], &g_Wc_lo[i]);
    }
}
__global__ void prep_wqv(const float* __restrict__ Wq,
                         const float* __restrict__ Wv) {
    long totq = (long)H_DIM * IH;
    long totv = (long)H_DIM * H_DIM;
    long stride = (long)gridDim.x * blockDim.x;
    for (long i = (long)blockIdx.x * blockDim.x + threadIdx.x; i < totq + totv; i += stride) {
        if (i < totq) {
            int n = (int)(i / IH), k = (int)(i % IH);
            split_store_h(Wq[(size_t)k * H_DIM + n], &g_Wq_hi[i], &g_Wq_lo[i]);
        } else {
            long j = i - totq;
            int n = (int)(j / H_DIM), k = (int)(j % H_DIM);
            split_store_h(Wv[(size_t)k * H_DIM + n], &g_Wv_hi[j], &g_Wv_lo[j]);
        }
    }
}

// ---------------- Phase A': ka (Q,V GEMMs) + kc1 (x|h partial preact) -------
// grid = 384 blocks x 128 threads.
// Blocks 0..63   : Q-GEMM (M=128,N=512,K=640), tile M32xN32, TK=64
// Blocks 64..127 : V-GEMM (M=128,N=512,K=512)
// Blocks 128..383: kc1 — preact partial over K=640 (x|h), writes g_pre
__global__ __launch_bounds__(128) void ka_kernel(
    int t, const float* __restrict__ bq, const float* __restrict__ bv)
{
    __shared__ __align__(16) __half Ah[2][32][72], Al[2][32][72];
    __shared__ __align__(16) __half Bh[2][32][72], Bl[2][32][72];

    const int blk = blockIdx.x;
    const int tid  = threadIdx.x;
    const int lane = tid & 31;
    const int warp = tid >> 5;
    const int mrow = (warp & 1) * 16;
    const int ncol = (warp >> 1) * 16;
    const int g    = lane >> 2, tg = lane & 3;

    const int a_r0 = (lane & 7) + ((lane >> 3) & 1) * 8;  // + mrow
    const int a_k = (lane >> 4) * 8;
    const int b_r0 = (lane & 7) + (lane >> 4) * 8;        // + ncol
    const int b_k = ((lane >> 3) & 1) * 8;

    const __half* __restrict__ xhi = g_x_hi + (size_t)t * B_DIM * I_DIM;
    const __half* __restrict__ xlo = g_x_lo + (size_t)t * B_DIM * I_DIM;
    const __half* __restrict__ hhi = g_h_hi[t & 1];
    const __half* __restrict__ hlo = g_h_lo[t & 1];

    float cHH[2][4] = {}, cLH[2][4] = {}, cHL[2][4] = {};

    if (blk < 128) {
        // ---------------- ka path ----------------
        const bool isQ = (blk < 64);
        const int bid = blk & 63;
        const int m0 = (bid >> 4) * 32;
        const int n0 = (bid & 15) * 32;
        const __half* __restrict__ WH = isQ ? g_Wq_hi : g_Wv_hi;
        const __half* __restrict__ WL = isQ ? g_Wq_lo : g_Wv_lo;
        const int Ktot = isQ ? IH : H_DIM;
        const int nt   = Ktot / 64;

        auto issue = [&](int it, int s) {
            const int kk = it * 64;
            #pragma unroll
            for (int l = 0; l < 2; l++) {
                int id = tid + l * 128;
                int r = id >> 3, c8 = (id & 7) * 8;
                const __half *ph, *pl;
                if (isQ) {
                    int gk = kk + c8;
                    if (gk < I_DIM) {
                        ph = xhi + (size_t)(m0 + r) * I_DIM + gk;
                        pl = xlo + (size_t)(m0 + r) * I_DIM + gk;
                    } else {
                        ph = hhi + (size_t)(m0 + r) * H_DIM + (gk - I_DIM);
                        pl = hlo + (size_t)(m0 + r) * H_DIM + (gk - I_DIM);
                    }
                } else {
                    ph = g_c_hi + (size_t)(m0 + r) * H_DIM + kk + c8;
                    pl = g_c_lo + (size_t)(m0 + r) * H_DIM + kk + c8;
                }
                cp16(&Ah[s][r][c8], ph);
                cp16(&Al[s][r][c8], pl);
            }
            #pragma unroll
            for (int l = 0; l < 2; l++) {
                int id = tid + l * 128;
                int r = id >> 3, c8 = (id & 7) * 8;
                size_t off = (size_t)(n0 + r) * Ktot + kk + c8;
                cp16(&Bh[s][r][c8], WH + off);
                cp16(&Bl[s][r][c8], WL + off);
            }
            cp_commit();
        };

        issue(0, 0);
        for (int it = 0; it < nt; it++) {
            const int s = it & 1;
            if (it + 1 < nt) { issue(it + 1, s ^ 1); cp_wait1(); }
            else             { cp_wait0(); }
            __syncthreads();
            #pragma unroll
            for (int ko = 0; ko < 64; ko += 16) {
                unsigned ah[4], al[4], bbh[4], bbl[4];
                ldsm4(ah,  smem_u32(&Ah[s][mrow + a_r0][ko + a_k]));
                ldsm4(al,  smem_u32(&Al[s][mrow + a_r0][ko + a_k]));
                ldsm4(bbh, smem_u32(&Bh[s][ncol + b_r0][ko + b_k]));
                ldsm4(bbl, smem_u32(&Bl[s][ncol + b_r0][ko + b_k]));
                hmma(cHH[0], ah, bbh[0], bbh[1]);
                hmma(cHH[1], ah, bbh[2], bbh[3]);
                hmma(cLH[0], al, bbh[0], bbh[1]);
                hmma(cLH[1], al, bbh[2], bbh[3]);
                hmma(cHL[0], ah, bbl[0], bbl[1]);
                hmma(cHL[1], ah, bbl[2], bbl[3]);
            }
            __syncthreads();
        }

        const float* bias = isQ ? bq : bv;
        float* outp = isQ ? g_Q : (g_V + (size_t)(t % W_WIN) * B_DIM * H_DIM);
        #pragma unroll
        for (int ns = 0; ns < 2; ns++) {
            float a0 = cHH[ns][0] + (cLH[ns][0] + cHL[ns][0]) * INV1024;
            float a1 = cHH[ns][1] + (cLH[ns][1] + cHL[ns][1]) * INV1024;
            float a2 = cHH[ns][2] + (cLH[ns][2] + cHL[ns][2]) * INV1024;
            float a3 = cHH[ns][3] + (cLH[ns][3] + cHL[ns][3]) * INV1024;
            int col = n0 + ncol + ns * 8 + 2 * tg;
            int r0 = m0 + mrow + g, r1 = r0 + 8;
            outp[(size_t)r0 * H_DIM + col]     = a0 + bias[col];
            outp[(size_t)r0 * H_DIM + col + 1] = a1 + bias[col + 1];
            outp[(size_t)r1 * H_DIM + col]     = a2 + bias[col];
            outp[(size_t)r1 * H_DIM + col + 1] = a3 + bias[col + 1];
        }
    } else {
        // ---------------- kc1 path: K=640 (x|h) partial preact -------------
        const int blk2 = blk - 128;
        const int m0 = (blk2 >> 6) * 32;   // 4 M-tiles
        const int j0 = (blk2 & 63) * 8;    // 64 j-tiles

        auto issue = [&](int it, int s) {
            const int kk = it * 64;
            const __half *Shi, *Slo; int ldA, koff;
            if (kk < I_DIM) { Shi = xhi; Slo = xlo; ldA = I_DIM; koff = kk; }
            else            { Shi = hhi; Slo = hlo; ldA = H_DIM; koff = kk - I_DIM; }
            #pragma unroll
            for (int l = 0; l < 2; l++) {
                int id = tid + l * 128;
                int r = id >> 3, c8 = (id & 7) * 8;
                cp16(&Ah[s][r][c8], Shi + (size_t)(m0 + r) * ldA + koff + c8);
                cp16(&Al[s][r][c8], Slo + (size_t)(m0 + r) * ldA + koff + c8);
            }
            #pragma unroll
            for (int l = 0; l < 2; l++) {
                int id = tid + l * 128;
                int r = id >> 3, c8 = (id & 7) * 8;
                int gn = (r >> 3) * H_DIM + j0 + (r & 7);
                size_t off = (size_t)gn * KC_K + kk + c8;
                cp16(&Bh[s][r][c8], g_Wc_hi + off);
                cp16(&Bl[s][r][c8], g_Wc_lo + off);
            }
            cp_commit();
        };

        const int nt = IH / 64;  // 10
        issue(0, 0);
        for (int it = 0; it < nt; it++) {
            const int s = it & 1;
            if (it + 1 < nt) { issue(it + 1, s ^ 1); cp_wait1(); }
            else             { cp_wait0(); }
            __syncthreads();
            #pragma unroll
            for (int ko = 0; ko < 64; ko += 16) {
                unsigned ah[4], al[4], bbh[4], bbl[4];
                ldsm4(ah,  smem_u32(&Ah[s][mrow + a_r0][ko + a_k]));
                ldsm4(al,  smem_u32(&Al[s][mrow + a_r0][ko + a_k]));
                ldsm4(bbh, smem_u32(&Bh[s][ncol + b_r0][ko + b_k]));
                ldsm4(bbl, smem_u32(&Bl[s][ncol + b_r0][ko + b_k]));
                hmma(cHH[0], ah, bbh[0], bbh[1]);
                hmma(cHH[1], ah, bbh[2], bbh[3]);
                hmma(cLH[0], al, bbh[0], bbh[1]);
                hmma(cLH[1], al, bbh[2], bbh[3]);
                hmma(cHL[0], ah, bbl[0], bbl[1]);
                hmma(cHL[1], ah, bbl[2], bbl[3]);
            }
            __syncthreads();
        }

        // write partial preact (pre-bias) to g_pre[b][gate*H + j]
        #pragma unroll
        for (int ns = 0; ns < 2; ns++) {
            float a0 = cHH[ns][0] + (cLH[ns][0] + cHL[ns][0]) * INV1024;
            float a1 = cHH[ns][1] + (cLH[ns][1] + cHL[ns][1]) * INV1024;
            float a2 = cHH[ns][2] + (cLH[ns][2] + cHL[ns][2]) * INV1024;
            float a3 = cHH[ns][3] + (cLH[ns][3] + cHL[ns][3]) * INV1024;
            int col = ncol + ns * 8 + 2 * tg;         // 0..31 within tile
            int gate = col >> 3, jj = col & 7;        // col+1 same gate
            int r0 = m0 + mrow + g, r1 = r0 + 8;
            size_t base = (size_t)gate * H_DIM + j0 + jj;
            g_pre[(size_t)r0 * G4H + base]     = a0;
            g_pre[(size_t)r0 * G4H + base + 1] = a1;
            g_pre[(size_t)r1 * G4H + base]     = a2;
            g_pre[(size_t)r1 * G4H + base + 1] = a3;
        }
    }
}

// ---------------- KB: scores -> softmax -> attn (writes attn splits) --------
__global__ __launch_bounds__(128) void kb_kernel(int t) {
    const float inv_sqrt_dk = 0.044194173824159216f; // 1/sqrt(512)
    int b = blockIdx.x;
    int tid = threadIdx.x;
    __shared__ float sQ[H_DIM];
    __shared__ float sS[W_WIN];
    __shared__ float sP[W_WIN];

    for (int j = tid; j < H_DIM; j += 128) sQ[j] = g_Q[(size_t)b * H_DIM + j];
    __syncthreads();

    int nv = (t + 1 < W_WIN) ? (t + 1) : W_WIN;
    int warp = tid / 32, lane = tid % 32;
    for (int w = warp; w < nv; w += 4) {
        const float* Vp = g_V + (size_t)(w * B_DIM + b) * H_DIM;
        float p = 0.f;
        for (int j = lane; j < H_DIM; j += 32) p += sQ[j] * Vp[j];
        #pragma unroll
        for (int o = 16; o > 0; o >>= 1) p += __shfl_xor_sync(0xffffffffu, p, o);
        if (lane == 0) sS[w] = p * inv_sqrt_dk;
    }
    __syncthreads();
    if (tid == 0) {
        float m = sS[0];
        for (int w = 1; w < nv; w++) m = fmaxf(m, sS[w]);
        float sum = 0.f;
        for (int w = 0; w < nv; w++) { float e = expf(sS[w] - m); sP[w] = e; sum += e; }
        float inv = 1.f / sum;
        for (int w = 0; w < nv; w++) sP[w] *= inv;
    }
    __syncthreads();
    for (int j = tid; j < H_DIM; j += 128) {
        float a = 0.f;
        for (int w = 0; w < nv; w++)
            a += sP[w] * g_V[(size_t)(w * B_DIM + b) * H_DIM + j];
        size_t idx = (size_t)b * H_DIM + j;
        split_store_h(a, &g_attn_hi[idx], &g_attn_lo[idx]);
    }
}

// ---------------- KC2: attn@Wa (K=512) + g_pre + biases + LSTM pointwise ----
// grid = 256 blocks (4 M-tiles x 64 j-tiles) x 128 threads. TK=64.
__global__ __launch_bounds__(128) void kc_kernel(
    int t,
    const float* __restrict__ bi, const float* __restrict__ ba,
    float* __restrict__ out)
{
    __shared__ __align__(16) __half Ah[2][32][72], Al[2][32][72];
    __shared__ __align__(16) __half Bh[2][32][72], Bl[2][32][72];
    __shared__ float sP[32][33];

    const int m0 = (blockIdx.x >> 6) * 32;
    const int j0 = (blockIdx.x & 63) * 8;

    __half* __restrict__ hohi = g_h_hi[(t + 1) & 1];
    __half* __restrict__ holo = g_h_lo[(t + 1) & 1];

    const int tid  = threadIdx.x;
    const int lane = tid & 31;
    const int warp = tid >> 5;
    const int mrow = (warp & 1) * 16;
    const int ncol = (warp >> 1) * 16;
    const int g    = lane >> 2, tg = lane & 3;

    const int a_r = mrow + (lane & 7) + ((lane >> 3) & 1) * 8;
    const int a_k = (lane >> 4) * 8;
    const int b_r = ncol + (lane & 7) + (lane >> 4) * 8;
    const int b_k = ((lane >> 3) & 1) * 8;

    auto issue = [&](int it, int s) {
        const int koff = it * 64;            // within attn segment
        #pragma unroll
        for (int l = 0; l < 2; l++) {
            int id = tid + l * 128;
            int r = id >> 3, c8 = (id & 7) * 8;
            cp16(&Ah[s][r][c8], g_attn_hi + (size_t)(m0 + r) * H_DIM + koff + c8);
            cp16(&Al[s][r][c8], g_attn_lo + (size_t)(m0 + r) * H_DIM + koff + c8);
        }
        #pragma unroll
        for (int l = 0; l < 2; l++) {
            int id = tid + l * 128;
            int r = id >> 3, c8 = (id & 7) * 8;
            int gn = (r >> 3) * H_DIM + j0 + (r & 7);
            size_t off = (size_t)gn * KC_K + IH + koff + c8;
            cp16(&Bh[s][r][c8], g_Wc_hi + off);
            cp16(&Bl[s][r][c8], g_Wc_lo + off);
        }
        cp_commit();
    };

    float cHH[2][4] = {}, cLH[2][4] = {}, cHL[2][4] = {};

    const int nt = H_DIM / 64;  // 8
    issue(0, 0);
    for (int it = 0; it < nt; it++) {
        const int s = it & 1;
        if (it + 1 < nt) { issue(it + 1, s ^ 1); cp_wait1(); }
        else             { cp_wait0(); }
        __syncthreads();
        #pragma unroll
        for (int ko = 0; ko < 64; ko += 16) {
            unsigned ah[4], al[4], bbh[4], bbl[4];
            ldsm4(ah,  smem_u32(&Ah[s][a_r][ko + a_k]));
            ldsm4(al,  smem_u32(&Al[s][a_r][ko + a_k]));
            ldsm4(bbh, smem_u32(&Bh[s][b_r][ko + b_k]));
            ldsm4(bbl, smem_u32(&Bl[s][b_r][ko + b_k]));
            hmma(cHH[0], ah, bbh[0], bbh[1]);
            hmma(cHH[1], ah, bbh[2], bbh[3]);
            hmma(cLH[0], al, bbh[0], bbh[1]);
            hmma(cLH[1], al, bbh[2], bbh[3]);
            hmma(cHL[0], ah, bbl[0], bbl[1]);
            hmma(cHL[1], ah, bbl[2], bbl[3]);
        }
        __syncthreads();
    }

    // combine own chains + partial from kc1, exchange through smem
    #pragma unroll
    for (int ns = 0; ns < 2; ns++) {
        int col0 = ncol + ns * 8 + 2 * tg;
        int gate = col0 >> 3, jj = col0 & 7;
        int r0 = m0 + mrow + g, r1 = r0 + 8;
        size_t base = (size_t)gate * H_DIM + j0 + jj;
        sP[mrow + g][col0]         = cHH[ns][0] + (cLH[ns][0] + cHL[ns][0]) * INV1024
                                     + g_pre[(size_t)r0 * G4H + base];
        sP[mrow + g][col0 + 1]     = cHH[ns][1] + (cLH[ns][1] + cHL[ns][1]) * INV1024
                                     + g_pre[(size_t)r0 * G4H + base + 1];
        sP[mrow + g + 8][col0]     = cHH[ns][2] + (cLH[ns][2] + cHL[ns][2]) * INV1024
                                     + g_pre[(size_t)r1 * G4H + base];
        sP[mrow + g + 8][col0 + 1] = cHH[ns][3] + (cLH[ns][3] + cHL[ns][3]) * INV1024
                                     + g_pre[(size_t)r1 * G4H + base + 1];
    }
    __syncthreads();

    const int row = tid >> 3;
    const int jj  = tid & 7;
    const int j   = j0 + jj;

    float bii = bi[j]             + ba[j];
    float bif = bi[H_DIM + j]     + ba[H_DIM + j];
    float bio = bi[2 * H_DIM + j] + ba[2 * H_DIM + j];
    float big = bi[3 * H_DIM + j] + ba[3 * H_DIM + j];

    #pragma unroll
    for (int half = 0; half < 2; half++) {
        int r = row + half * 16;
        int b = m0 + r;
        float pi = sP[r][jj]      + bii;
        float pf = sP[r][8 + jj]  + bif;
        float po = sP[r][16 + jj] + bio;
        float pg = sP[r][24 + jj] + big;

        float ig = 1.f / (1.f + expf(-pi));
        float fg = 1.f / (1.f + expf(-pf));
        float og = 1.f / (1.f + expf(-po));
        float gg = tanhf(pg);

        size_t idx = (size_t)b * H_DIM + j;
        float cn = g_c[idx] * fg + ig * gg;
        float hn = og * tanhf(cn);

        g_c[idx] = cn;
        split_store_h(cn, &g_c_hi[idx], &g_c_lo[idx]);
        split_store_h(hn, &hohi[idx], &holo[idx]);
        out[(size_t)t * B_DIM * H_DIM + idx] = hn;
    }
}

// ---------------- launcher --------------------------------------------------
extern "C" void kernel_launch(void* const* d_in, const int* in_sizes, int n_in,
                              void* d_out, int out_size) {
    const float* x  = (const float*)d_in[0];
    const float* Wi = (const float*)d_in[1];
    const float* bi = (const float*)d_in[2];
    const float* Wh = (const float*)d_in[3];
    const float* Wv = (const float*)d_in[4];
    const float* bv = (const float*)d_in[5];
    const float* Wq = (const float*)d_in[6];
    const float* bq = (const float*)d_in[7];
    const float* Wa = (const float*)d_in[8];
    const float* ba = (const float*)d_in[9];
    float* out = (float*)d_out;

    init_kernel<<<1024, 256>>>(bv);
    prep_x<<<2048, 256>>>(x);
    prep_wc<<<2048, 256>>>(Wi, Wh, Wa);
    prep_wqv<<<1024, 256>>>(Wq, Wv);
    for (int t = 0; t < T_LEN; t++) {
        ka_kernel<<<384, 128>>>(t, bq, bv);
        kb_kernel<<<128, 128>>>(t);
        kc_kernel<<<256, 128>>>(t, bi, ba, out);
    }
}